// round 12
// baseline (speedup 1.0000x reference)
#include <cuda_runtime.h>
#include <cuda_bf16.h>
#include <cuda_fp16.h>
#include <math.h>
#include <stdint.h>
#include <string.h>

#define N_PANO 50000
#define N_FP   10000
#define HID    128
#define E_PP   800000
#define E_PF   50000

#define SCAN_BPP 49
#define SCAN_BFP 10
#define SCAN_BLKS (SCAN_BPP + SCAN_BFP)
#define SCAN_FLAG (1 << 30)

#define GEMM_MBLKS 391        // ceil(50000/128)
#define EALL_BLKS  3321       // ceil(850000/256)

typedef unsigned short ushort_t;

// ---------------- device scratch (static, no allocation) ----------------
// activation split-bf16 images (padded by 128 rows: cp.async may prefetch past M)
__device__ ushort_t g_ahi[(N_PANO + 128) * 128];
__device__ ushort_t g_alo[(N_PANO + 128) * 128];
__device__ ushort_t g_hsh[N_PANO * HID];    // hs fp16 (gather payload)
__device__ ushort_t g_linh[N_PANO * HID];   // lin fp16
__device__ float g_es[N_PANO];
__device__ float g_ed[N_PANO];
__device__ float g_es2[N_PANO];
__device__ float g_ed2[N_PANO];
__device__ float g_es3[N_PANO];
__device__ float g_edfp[N_FP];
__device__ float g_wc[704];
// split-bf16 weight images, [N][K] row-major
__device__ ushort_t g_wb0hi[256 * 128], g_wb0lo[256 * 128];
__device__ ushort_t g_wb1hi[256 * 128], g_wb1lo[256 * 128];
__device__ ushort_t g_wbthi[64 * 128],  g_wbtlo[64 * 128];
// CSR build
__device__ int g_cnt[N_PANO];
__device__ int g_off[N_PANO + 1];
__device__ int g_cur[N_PANO];
__device__ int g_srt[E_PP];
__device__ int g_cnt_fp[N_FP];
__device__ int g_off_fp[N_FP + 1];
__device__ int g_cur_fp[N_FP];
__device__ int g_srt_fp[E_PF];
__device__ int g_flagged[SCAN_BLKS];        // aggregate | SCAN_FLAG (decoupled lookback)

// ---------------- helpers ----------------
__device__ __forceinline__ uint32_t smem_u32(const void* p) {
    uint32_t a;
    asm("{ .reg .u64 t; cvta.to.shared.u64 t, %1; cvt.u32.u64 %0, t; }" : "=r"(a) : "l"(p));
    return a;
}
__device__ __forceinline__ void cp16(uint32_t s, const void* g) {
    asm volatile("cp.async.ca.shared.global [%0], [%1], 16;" :: "r"(s), "l"(g) : "memory");
}
__device__ __forceinline__ void ldsm_x4(uint32_t* r, uint32_t addr) {
    asm volatile("ldmatrix.sync.aligned.m8n8.x4.shared.b16 {%0,%1,%2,%3}, [%4];"
                 : "=r"(r[0]), "=r"(r[1]), "=r"(r[2]), "=r"(r[3]) : "r"(addr));
}
__device__ __forceinline__ void ldsm_x2(uint32_t* r, uint32_t addr) {
    asm volatile("ldmatrix.sync.aligned.m8n8.x2.shared.b16 {%0,%1}, [%2];"
                 : "=r"(r[0]), "=r"(r[1]) : "r"(addr));
}
__device__ __forceinline__ void mma16816(float* d, const uint32_t* a, const uint32_t* b) {
    asm volatile("mma.sync.aligned.m16n8k16.row.col.f32.bf16.bf16.f32 "
                 "{%0,%1,%2,%3}, {%4,%5,%6,%7}, {%8,%9}, {%0,%1,%2,%3};"
                 : "+f"(d[0]), "+f"(d[1]), "+f"(d[2]), "+f"(d[3])
                 : "r"(a[0]), "r"(a[1]), "r"(a[2]), "r"(a[3]), "r"(b[0]), "r"(b[1]));
}
__device__ __forceinline__ void split_bf16(float v, ushort_t& h, ushort_t& l) {
    __nv_bfloat16 hb = __float2bfloat16(v);
    float r = v - __bfloat162float(hb);
    __nv_bfloat16 lb = __float2bfloat16(r);
    memcpy(&h, &hb, 2); memcpy(&l, &lb, 2);
}

// ---------------- GEMM body: cp.async 2-stage pipelined, split-bf16 3 terms ----------------
template<int NT>
__device__ __forceinline__ void gemm_body(
        int bx, int by,
        const ushort_t* __restrict__ Ahi, const ushort_t* __restrict__ Alo,
        const ushort_t* __restrict__ Bhi, const ushort_t* __restrict__ Blo,
        ushort_t* __restrict__ C1h, ushort_t* __restrict__ C2h, int M, char* smem) {
    constexpr int NTW = NT / 4;
    constexpr int NTILES = NTW / 8;
    constexpr int A_BYTES = 128 * 80;                 // one image (hi OR lo) per stage
    constexpr int STAGE = 2 * A_BYTES + 2 * NT * 80;  // A hi+lo, B hi+lo
    const int tid = threadIdx.x;
    const int wid = tid >> 5, lane = tid & 31;
    const int wm = wid >> 2, wn = wid & 3;
    const int m0 = bx * 128;
    const int nb = by * 128;

    float d[4][NTILES][4];
    #pragma unroll
    for (int mt = 0; mt < 4; mt++)
        #pragma unroll
        for (int nt = 0; nt < NTILES; nt++)
            #pragma unroll
            for (int j = 0; j < 4; j++) d[mt][nt][j] = 0.f;

    auto copy_stage = [&](int stg, int k0) {
        char* base = smem + stg * STAGE;
        #pragma unroll
        for (int l = 0; l < 2; l++) {
            int c = tid + l * 256;           // 0..511 chunks of 16B
            int r = c >> 2, q = c & 3;
            cp16(smem_u32(base + r * 80 + q * 16),
                 Ahi + (size_t)(m0 + r) * 128 + k0 + q * 8);
            cp16(smem_u32(base + A_BYTES + r * 80 + q * 16),
                 Alo + (size_t)(m0 + r) * 128 + k0 + q * 8);
        }
        #pragma unroll
        for (int l = 0; l < (NT * 4) / 256; l++) {
            int c = tid + l * 256;
            int r = c >> 2, q = c & 3;
            cp16(smem_u32(base + 2 * A_BYTES + r * 80 + q * 16),
                 Bhi + (size_t)(nb + r) * 128 + k0 + q * 8);
            cp16(smem_u32(base + 2 * A_BYTES + NT * 80 + r * 80 + q * 16),
                 Blo + (size_t)(nb + r) * 128 + k0 + q * 8);
        }
        asm volatile("cp.async.commit_group;" ::: "memory");
    };

    auto compute_stage = [&](int stg) {
        char* base = smem + stg * STAGE;
        #pragma unroll
        for (int kk = 0; kk < 32; kk += 16) {
            uint32_t ah[4][4], al[4][4], bh[NTILES][2], bl[NTILES][2];
            #pragma unroll
            for (int mt = 0; mt < 4; mt++) {
                int ar = wm * 64 + mt * 16 + (lane & 15);
                int ac = kk + (lane >> 4) * 8;
                ldsm_x4(ah[mt], smem_u32(base + ar * 80 + ac * 2));
                ldsm_x4(al[mt], smem_u32(base + A_BYTES + ar * 80 + ac * 2));
            }
            #pragma unroll
            for (int nt = 0; nt < NTILES; nt++) {
                int l16 = lane & 15;
                int br = wn * NTW + nt * 8 + (l16 & 7);
                int bc = kk + (l16 >> 3) * 8;
                ldsm_x2(bh[nt], smem_u32(base + 2 * A_BYTES + br * 80 + bc * 2));
                ldsm_x2(bl[nt], smem_u32(base + 2 * A_BYTES + NT * 80 + br * 80 + bc * 2));
            }
            #pragma unroll
            for (int mt = 0; mt < 4; mt++)
                #pragma unroll
                for (int nt = 0; nt < NTILES; nt++) {
                    mma16816(d[mt][nt], ah[mt], bh[nt]);
                    mma16816(d[mt][nt], al[mt], bh[nt]);
                    mma16816(d[mt][nt], ah[mt], bl[nt]);
                }
        }
    };

    copy_stage(0, 0);
    #pragma unroll
    for (int i = 0; i < 4; i++) {
        if (i < 3) copy_stage((i + 1) & 1, (i + 1) * 32);
        if (i < 3) { asm volatile("cp.async.wait_group 1;" ::: "memory"); }
        else       { asm volatile("cp.async.wait_group 0;" ::: "memory"); }
        __syncthreads();
        compute_stage(i & 1);
        __syncthreads();
    }

    ushort_t* C = (NT == 64 || by == 0) ? C1h : C2h;
    const int cstride = (NT == 64) ? 64 : 128;
    #pragma unroll
    for (int mt = 0; mt < 4; mt++) {
        int r0 = m0 + wm * 64 + mt * 16 + (lane >> 2);
        #pragma unroll
        for (int nt = 0; nt < NTILES; nt++) {
            int c = wn * NTW + nt * 8 + (lane & 3) * 2;
            if (r0 < M)
                *reinterpret_cast<__half2*>(&C[(size_t)r0 * cstride + c]) =
                    __floats2half2_rn(d[mt][nt][0], d[mt][nt][1]);
            if (r0 + 8 < M)
                *reinterpret_cast<__half2*>(&C[(size_t)(r0 + 8) * cstride + c]) =
                    __floats2half2_rn(d[mt][nt][2], d[mt][nt][3]);
        }
    }
}

template<int NT>
__global__ void __launch_bounds__(256) mmagemm_kernel(
        const ushort_t* __restrict__ Ahi, const ushort_t* __restrict__ Alo,
        const ushort_t* __restrict__ Bhi, const ushort_t* __restrict__ Blo,
        ushort_t* __restrict__ C1h, ushort_t* __restrict__ C2h, int M) {
    extern __shared__ char smem[];
    gemm_body<NT>(blockIdx.x, blockIdx.y, Ahi, Alo, Bhi, Blo, C1h, C2h, M, smem);
}

// ---------------- K1: weight prep + compose + zero counters/flags ----------------
__global__ void __launch_bounds__(256) prep_all_kernel(
        const float* __restrict__ Ws0, const float* __restrict__ as0,
        const float* __restrict__ Wd0, const float* __restrict__ ad0,
        const float* __restrict__ Lw0,
        const float* __restrict__ Ws1, const float* __restrict__ as1,
        const float* __restrict__ Wd1, const float* __restrict__ ad1,
        const float* __restrict__ Lw1,
        const float* __restrict__ Wts, const float* __restrict__ ats,
        const float* __restrict__ Wtd, const float* __restrict__ atd) {
    int blk = blockIdx.x;
    int t = threadIdx.x;
    if (blk < 288) {
        int idx = blk * 256 + t;
        ushort_t *ih, *il;
        int n, k;
        float v;
        if (idx < 32768) {
            n = idx >> 7; k = idx & 127;
            v = (n < 128) ? Ws0[k * 128 + n] : Lw0[k * 128 + (n - 128)];
            ih = g_wb0hi; il = g_wb0lo;
        } else if (idx < 65536) {
            int e = idx - 32768;
            n = e >> 7; k = e & 127;
            v = (n < 128) ? Ws1[k * 128 + n] : Lw1[k * 128 + (n - 128)];
            ih = g_wb1hi; il = g_wb1lo;
        } else {
            int e = idx - 65536;
            n = e >> 7; k = e & 127;
            v = Wts[k * 64 + n];
            ih = g_wbthi; il = g_wbtlo;
        }
        ushort_t h, l;
        split_bf16(v, h, l);
        ih[n * 128 + k] = h;
        il[n * 128 + k] = l;
    } else if (blk < 291) {
        int b = blk - 288;
        if (b == 0) {
            if (t < 128) {
                float s = 0.f;
                for (int n = 0; n < 128; n++) s += Ws0[t * 128 + n] * as0[n];
                g_wc[t] = s;
            } else {
                int i = t - 128; float s = 0.f;
                for (int n = 0; n < 128; n++) s += Wd0[i * 128 + n] * ad0[n];
                g_wc[128 + i] = s;
            }
        } else if (b == 1) {
            if (t < 128) {
                float s = 0.f;
                for (int n = 0; n < 128; n++) s += Ws1[t * 128 + n] * as1[n];
                g_wc[256 + t] = s;
            } else {
                int i = t - 128; float s = 0.f;
                for (int n = 0; n < 128; n++) s += Wd1[i * 128 + n] * ad1[n];
                g_wc[384 + i] = s;
            }
        } else {
            if (t < 128) {
                float s = 0.f;
                for (int n = 0; n < 64; n++) s += Wts[t * 64 + n] * ats[n];
                g_wc[512 + t] = s;
            } else if (t < 192) {
                int i = t - 128; float s = 0.f;
                for (int n = 0; n < 64; n++) s += Wtd[i * 64 + n] * atd[n];
                g_wc[640 + i] = s;
            }
        }
    } else {
        int i = (blk - 291) * 256 + t;
        if (i < N_PANO) g_cnt[i] = 0;
        else if (i < N_PANO + N_FP) g_cnt_fp[i - N_PANO] = 0;
        else if (i < N_PANO + N_FP + SCAN_BLKS) g_flagged[i - N_PANO - N_FP] = 0;
    }
}

// ---------------- K2: vectorized histogram + attention dot GEMVs (+ x_pano split) ----------------
#define K2_HPP   782                       // ceil(200000 int4-groups / 256)
#define K2_HIST  (K2_HPP + 49)             // 831
#define K2_GEMV2 (K2_HIST + 6250)          // 7081
#define K2_TOTAL (K2_GEMV2 + 1250)         // 8331
__global__ void __launch_bounds__(256) hist_gemv_kernel(
        const int* __restrict__ dst_pp, const int* __restrict__ dst_pf,
        const float* __restrict__ X, const float* __restrict__ Xfp) {
    int blk = blockIdx.x;
    int t = threadIdx.x;
    if (blk < K2_HPP) {
        int g = blk * 256 + t;
        if (g * 4 < E_PP) {
            int4 d = *(const int4*)&dst_pp[g * 4];
            atomicAdd(&g_cnt[d.x], 1);
            atomicAdd(&g_cnt[d.y], 1);
            atomicAdd(&g_cnt[d.z], 1);
            atomicAdd(&g_cnt[d.w], 1);
        }
    } else if (blk < K2_HIST) {
        int g = (blk - K2_HPP) * 256 + t;
        if (g * 4 < E_PF) {
            int4 d = *(const int4*)&dst_pf[g * 4];
            atomicAdd(&g_cnt_fp[d.x], 1);
            atomicAdd(&g_cnt_fp[d.y], 1);
            atomicAdd(&g_cnt_fp[d.z], 1);
            atomicAdd(&g_cnt_fp[d.w], 1);
        }
    } else if (blk < K2_GEMV2) {
        int gw = ((blk - K2_HIST) * 256 + t) >> 5;
        int lane = t & 31;
        if (gw >= N_PANO) return;
        float4 x = *(const float4*)&X[(size_t)gw * 128 + lane * 4];
        // split x_pano to bf16 hi/lo images for the layer-0 GEMM
        ushort4 h4, l4;
        split_bf16(x.x, h4.x, l4.x); split_bf16(x.y, h4.y, l4.y);
        split_bf16(x.z, h4.z, l4.z); split_bf16(x.w, h4.w, l4.w);
        *(ushort4*)&g_ahi[(size_t)gw * 128 + lane * 4] = h4;
        *(ushort4*)&g_alo[(size_t)gw * 128 + lane * 4] = l4;
        float4 a = *(const float4*)&g_wc[0 + lane * 4];
        float4 b = *(const float4*)&g_wc[128 + lane * 4];
        float sa = x.x * a.x + x.y * a.y + x.z * a.z + x.w * a.w;
        float sb = x.x * b.x + x.y * b.y + x.z * b.z + x.w * b.w;
        #pragma unroll
        for (int o = 16; o; o >>= 1) {
            sa += __shfl_xor_sync(0xFFFFFFFFu, sa, o);
            sb += __shfl_xor_sync(0xFFFFFFFFu, sb, o);
        }
        if (lane == 0) { g_es[gw] = sa; g_ed[gw] = sb; }
    } else {
        int gw = ((blk - K2_GEMV2) * 256 + t) >> 5;
        int lane = t & 31;
        if (gw >= N_FP) return;
        float2 x = *(const float2*)&Xfp[(size_t)gw * 64 + lane * 2];
        float2 a = *(const float2*)&g_wc[640 + lane * 2];
        float s = x.x * a.x + x.y * a.y;
        #pragma unroll
        for (int o = 16; o; o >>= 1) s += __shfl_xor_sync(0xFFFFFFFFu, s, o);
        if (lane == 0) g_edfp[gw] = s;
    }
}

// ---- K3: fused scan (tile scan + decoupled lookback + offset add) ----
__global__ void __launch_bounds__(256) scan_fused_kernel() {
    __shared__ int woff[9];
    __shared__ int s_bo;
    __shared__ int s_tot;
    int blk = blockIdx.x;
    bool fp = blk >= SCAN_BPP;
    const int N = fp ? N_FP : N_PANO;
    const int* cnt = fp ? g_cnt_fp : g_cnt;
    int* off = fp ? g_off_fp : g_off;
    int* cur = fp ? g_cur_fp : g_cur;
    int seg0 = fp ? SCAN_BPP : 0;
    int segN = fp ? SCAN_BLKS : SCAN_BPP;
    int base = (fp ? blk - SCAN_BPP : blk) * 1024;
    int t = threadIdx.x;
    int lane = t & 31, wid = t >> 5;
    int idx = base + t * 4;
    int4 v = make_int4(0, 0, 0, 0);
    if (idx < N) v = *(const int4*)&cnt[idx];
    int s0 = v.x, s1 = v.x + v.y, s2 = s1 + v.z, tot = s2 + v.w;
    int inc = tot;
    #pragma unroll
    for (int o = 1; o < 32; o <<= 1) {
        int n = __shfl_up_sync(0xFFFFFFFFu, inc, o);
        if (lane >= o) inc += n;
    }
    if (lane == 31) woff[wid] = inc;
    __syncthreads();
    if (t == 0) {
        int run = 0;
        #pragma unroll
        for (int j = 0; j < 8; j++) { int x = woff[j]; woff[j] = run; run += x; }
        s_tot = run;
        atomicExch(&g_flagged[blk], run | SCAN_FLAG);
        s_bo = 0;
    }
    __syncthreads();
    if (t < blk - seg0) {
        int j = seg0 + t;
        int w;
        do { w = atomicAdd(&g_flagged[j], 0); } while (!(w & SCAN_FLAG));
        atomicAdd(&s_bo, w & (SCAN_FLAG - 1));
    }
    __syncthreads();
    int bo = s_bo;
    if (t == 0 && blk == segN - 1) off[N] = bo + s_tot;
    int exc = bo + woff[wid] + inc - tot;
    if (idx < N) {
        int4 o = make_int4(exc, exc + s0, exc + s1, exc + s2);
        *(int4*)&off[idx] = o;
        *(int4*)&cur[idx] = o;
    }
}

// ---------------- K4: layer-0 GEMM fused with edge scatter ----------------
__global__ void __launch_bounds__(256) gemm0_scatter_kernel(
        const ushort_t* __restrict__ Ahi, const ushort_t* __restrict__ Alo,
        const ushort_t* __restrict__ Bhi, const ushort_t* __restrict__ Blo,
        ushort_t* __restrict__ C1h, ushort_t* __restrict__ C2h,
        const int* __restrict__ src_pp, const int* __restrict__ dst_pp,
        const int* __restrict__ src_pf, const int* __restrict__ dst_pf) {
    extern __shared__ char smem[];
    int blk = blockIdx.x;
    if (blk < 2 * GEMM_MBLKS) {
        gemm_body<128>(blk % GEMM_MBLKS, blk / GEMM_MBLKS, Ahi, Alo, Bhi, Blo,
                       C1h, C2h, N_PANO, smem);
    } else {
        int i = (blk - 2 * GEMM_MBLKS) * 256 + threadIdx.x;
        if (i < E_PP) {
            int pos = atomicAdd(&g_cur[dst_pp[i]], 1);
            g_srt[pos] = src_pp[i];
        } else if (i < E_PP + E_PF) {
            int j = i - E_PP;
            int pos = atomicAdd(&g_cur_fp[dst_pf[j]], 1);
            g_srt_fp[pos] = src_pf[j];
        }
    }
}

// ---------------- CSR aggregation + finalize + next-stage dots + bf16 split ----------------
__global__ void __launch_bounds__(256) agg_pp_kernel(const float* __restrict__ b,
                                                     const float* __restrict__ Lb,
                                                     const float* __restrict__ es_in,
                                                     const float* __restrict__ ed_in,
                                                     const float* __restrict__ wa,
                                                     const float* __restrict__ wb,
                                                     float* __restrict__ ea,
                                                     float* __restrict__ eb) {
    int gw = (blockIdx.x * blockDim.x + threadIdx.x) >> 5;
    int lane = threadIdx.x & 31;
    if (gw >= N_PANO) return;
    int start = g_off[gw];
    int end   = g_off[gw + 1];
    float edd = ed_in[gw];
    float4 acc = make_float4(0.f, 0.f, 0.f, 0.f);
    float exsum = 0.f;
    for (int base = start; base < end; base += 32) {
        int m = end - base; if (m > 32) m = 32;
        int s = 0; float ex = 0.f;
        if (lane < m) {
            s = g_srt[base + lane];
            float ez = es_in[s] + edd;
            float e = ez > 0.f ? ez : 0.2f * ez;
            ex = __expf(e);
        }
        exsum += ex;
        for (int j = 0; j < m; j++) {
            int sj   = __shfl_sync(0xFFFFFFFFu, s, j);
            float xj = __shfl_sync(0xFFFFFFFFu, ex, j);
            uint2 hp = *(const uint2*)&g_hsh[(size_t)sj * 128 + lane * 4];
            float2 f0 = __half22float2(*reinterpret_cast<const __half2*>(&hp.x));
            float2 f1 = __half22float2(*reinterpret_cast<const __half2*>(&hp.y));
            acc.x += f0.x * xj; acc.y += f0.y * xj;
            acc.z += f1.x * xj; acc.w += f1.y * xj;
        }
    }
    #pragma unroll
    for (int o = 16; o; o >>= 1) exsum += __shfl_xor_sync(0xFFFFFFFFu, exsum, o);
    float inv = exsum > 0.f ? 1.f / exsum : 0.f;
    uint2 lp = *(const uint2*)&g_linh[(size_t)gw * 128 + lane * 4];
    float2 l0 = __half22float2(*reinterpret_cast<const __half2*>(&lp.x));
    float2 l1 = __half22float2(*reinterpret_cast<const __half2*>(&lp.y));
    float4 bb = *(const float4*)&b[lane * 4];
    float4 lb = *(const float4*)&Lb[lane * 4];
    float4 r;
    r.x = fmaxf(acc.x * inv + bb.x + l0.x + lb.x, 0.f);
    r.y = fmaxf(acc.y * inv + bb.y + l0.y + lb.y, 0.f);
    r.z = fmaxf(acc.z * inv + bb.z + l1.x + lb.z, 0.f);
    r.w = fmaxf(acc.w * inv + bb.w + l1.y + lb.w, 0.f);
    // split h to bf16 hi/lo images for the next GEMM (fp32 h not needed elsewhere)
    ushort4 h4, l4;
    split_bf16(r.x, h4.x, l4.x); split_bf16(r.y, h4.y, l4.y);
    split_bf16(r.z, h4.z, l4.z); split_bf16(r.w, h4.w, l4.w);
    *(ushort4*)&g_ahi[(size_t)gw * 128 + lane * 4] = h4;
    *(ushort4*)&g_alo[(size_t)gw * 128 + lane * 4] = l4;
    // fused attention dots for the next stage
    float4 a4 = *(const float4*)&wa[lane * 4];
    float sa = r.x * a4.x + r.y * a4.y + r.z * a4.z + r.w * a4.w;
    float sb = 0.f;
    if (eb) {
        float4 b4 = *(const float4*)&wb[lane * 4];
        sb = r.x * b4.x + r.y * b4.y + r.z * b4.z + r.w * b4.w;
    }
    #pragma unroll
    for (int o = 16; o; o >>= 1) {
        sa += __shfl_xor_sync(0xFFFFFFFFu, sa, o);
        sb += __shfl_xor_sync(0xFFFFFFFFu, sb, o);
    }
    if (lane == 0) {
        ea[gw] = sa;
        if (eb) eb[gw] = sb;
    }
}

__global__ void __launch_bounds__(256) agg_pf_kernel(const float* __restrict__ bt,
                                                     float* __restrict__ out) {
    int gw = (blockIdx.x * blockDim.x + threadIdx.x) >> 5;
    int lane = threadIdx.x & 31;
    if (gw >= N_FP) return;
    int start = g_off_fp[gw];
    int end   = g_off_fp[gw + 1];
    float edd = g_edfp[gw];
    float2 acc = make_float2(0.f, 0.f);
    float exsum = 0.f;
    for (int base = start; base < end; base += 32) {
        int m = end - base; if (m > 32) m = 32;
        int s = 0; float ex = 0.f;
        if (lane < m) {
            s = g_srt_fp[base + lane];
            float ez = g_es3[s] + edd;
            float e = ez > 0.f ? ez : 0.2f * ez;
            ex = __expf(e);
        }
        exsum += ex;
        for (int j = 0; j < m; j++) {
            int sj   = __shfl_sync(0xFFFFFFFFu, s, j);
            float xj = __shfl_sync(0xFFFFFFFFu, ex, j);
            uint32_t hp = *(const uint32_t*)&g_hsh[(size_t)sj * 64 + lane * 2];
            float2 f = __half22float2(*reinterpret_cast<const __half2*>(&hp));
            acc.x += f.x * xj; acc.y += f.y * xj;
        }
    }
    #pragma unroll
    for (int o = 16; o; o >>= 1) exsum += __shfl_xor_sync(0xFFFFFFFFu, exsum, o);
    float inv = exsum > 0.f ? 1.f / exsum : 0.f;
    float2 bb = *(const float2*)&bt[lane * 2];
    *(float2*)&out[(size_t)gw * 64 + lane * 2] = make_float2(acc.x * inv + bb.x,
                                                             acc.y * inv + bb.y);
}

// ---------------- launch ----------------
extern "C" void kernel_launch(void* const* d_in, const int* in_sizes, int n_in,
                              void* d_out, int out_size) {
    const float* x_pano = (const float*)d_in[0];
    const float* x_fp   = (const float*)d_in[1];
    const float* Ws0 = (const float*)d_in[2];
    const float* Wd0 = (const float*)d_in[3];
    const float* as0 = (const float*)d_in[4];
    const float* ad0 = (const float*)d_in[5];
    const float* b0  = (const float*)d_in[6];
    const float* Lw0 = (const float*)d_in[7];
    const float* Lb0 = (const float*)d_in[8];
    const float* Ws1 = (const float*)d_in[9];
    const float* Wd1 = (const float*)d_in[10];
    const float* as1 = (const float*)d_in[11];
    const float* ad1 = (const float*)d_in[12];
    const float* b1  = (const float*)d_in[13];
    const float* Lw1 = (const float*)d_in[14];
    const float* Lb1 = (const float*)d_in[15];
    const float* Wts = (const float*)d_in[16];
    const float* Wtd = (const float*)d_in[17];
    const float* ats = (const float*)d_in[18];
    const float* atd = (const float*)d_in[19];
    const float* bt  = (const float*)d_in[20];
    const int* edge_pp = (const int*)d_in[21];
    const int* pf_src  = (const int*)d_in[22];
    const int* pf_dst  = (const int*)d_in[23];
    const int* pp_src = edge_pp;
    const int* pp_dst = edge_pp + E_PP;

    float *p_es, *p_ed, *p_es2, *p_ed2, *p_es3, *p_wc;
    cudaGetSymbolAddress((void**)&p_es,   g_es);
    cudaGetSymbolAddress((void**)&p_ed,   g_ed);
    cudaGetSymbolAddress((void**)&p_es2,  g_es2);
    cudaGetSymbolAddress((void**)&p_ed2,  g_ed2);
    cudaGetSymbolAddress((void**)&p_es3,  g_es3);
    cudaGetSymbolAddress((void**)&p_wc,   g_wc);
    ushort_t *p_ahi, *p_alo, *p_hsh, *p_linh;
    ushort_t *p_b0hi, *p_b0lo, *p_b1hi, *p_b1lo, *p_bthi, *p_btlo;
    cudaGetSymbolAddress((void**)&p_ahi,  g_ahi);
    cudaGetSymbolAddress((void**)&p_alo,  g_alo);
    cudaGetSymbolAddress((void**)&p_hsh,  g_hsh);
    cudaGetSymbolAddress((void**)&p_linh, g_linh);
    cudaGetSymbolAddress((void**)&p_b0hi, g_wb0hi);
    cudaGetSymbolAddress((void**)&p_b0lo, g_wb0lo);
    cudaGetSymbolAddress((void**)&p_b1hi, g_wb1hi);
    cudaGetSymbolAddress((void**)&p_b1lo, g_wb1lo);
    cudaGetSymbolAddress((void**)&p_bthi, g_wbthi);
    cudaGetSymbolAddress((void**)&p_btlo, g_wbtlo);

    const int SM128 = 2 * (2 * 128 * 80 + 2 * 128 * 80);   // 81920
    const int SM64  = 2 * (2 * 128 * 80 + 2 * 64 * 80);    // 61440
    cudaFuncSetAttribute(gemm0_scatter_kernel, cudaFuncAttributeMaxDynamicSharedMemorySize, SM128);
    cudaFuncSetAttribute(mmagemm_kernel<128>,  cudaFuncAttributeMaxDynamicSharedMemorySize, SM128);
    cudaFuncSetAttribute(mmagemm_kernel<64>,   cudaFuncAttributeMaxDynamicSharedMemorySize, SM64);

    // K1: weight prep + compose + zero counters/flags
    prep_all_kernel<<<527, 256>>>(Ws0, as0, Wd0, ad0, Lw0,
                                  Ws1, as1, Wd1, ad1, Lw1,
                                  Wts, ats, Wtd, atd);
    // K2: vectorized histogram + attention dots + x_pano split
    hist_gemv_kernel<<<K2_TOTAL, 256>>>(pp_dst, pf_dst, x_pano, x_fp);
    // K3: fused scan (decoupled lookback)
    scan_fused_kernel<<<SCAN_BLKS, 256>>>();
    // K4: layer-0 GEMM (pipelined) + edge scatter (overlapped)
    gemm0_scatter_kernel<<<2 * GEMM_MBLKS + EALL_BLKS, 256, SM128>>>(
        p_ahi, p_alo, p_b0hi, p_b0lo, p_hsh, p_linh,
        pp_src, pp_dst, pf_src, pf_dst);
    // layer 0 aggregation (writes next-layer A images)
    agg_pp_kernel<<<6250, 256>>>(b0, Lb0, p_es, p_ed, p_wc + 256, p_wc + 384, p_es2, p_ed2);
    // layer 1
    mmagemm_kernel<128><<<dim3(GEMM_MBLKS, 2), 256, SM128>>>(p_ahi, p_alo, p_b1hi, p_b1lo,
                                                             p_hsh, p_linh, N_PANO);
    agg_pp_kernel<<<6250, 256>>>(b1, Lb1, p_es2, p_ed2, p_wc + 512, (const float*)0,
                                 p_es3, (float*)0);
    // translate
    mmagemm_kernel<64><<<dim3(GEMM_MBLKS, 1), 256, SM64>>>(p_ahi, p_alo, p_bthi, p_btlo,
                                                           p_hsh, (ushort_t*)0, N_PANO);
    agg_pf_kernel<<<1250, 256>>>(bt, (float*)d_out);
}

// round 13
// speedup vs baseline: 1.0795x; 1.0795x over previous
#include <cuda_runtime.h>
#include <cuda_bf16.h>
#include <cuda_fp16.h>
#include <math.h>
#include <stdint.h>
#include <string.h>

#define N_PANO 50000
#define N_FP   10000
#define HID    128
#define E_PP   800000
#define E_PF   50000

#define SCAN_BPP 49
#define SCAN_BFP 10
#define SCAN_BLKS (SCAN_BPP + SCAN_BFP)
#define SCAN_FLAG (1 << 30)

#define GEMM_MBLKS 391        // ceil(50000/128)
#define FP_MBLKS   79         // ceil(10000/128)
#define EALL_BLKS  3321       // ceil(850000/256)

typedef unsigned short ushort_t;

// ---------------- device scratch (static, no allocation) ----------------
__device__ float    g_h[N_PANO * HID];      // fp32 activations (GEMM A input)
__device__ ushort_t g_hsh[N_PANO * HID];    // hs fp16 (gather payload)
__device__ ushort_t g_h2h[N_PANO * HID];    // h2 fp16 (translate gather payload)
__device__ ushort_t g_linh[N_PANO * HID];   // lin fp16
__device__ float    g_c[N_FP * 128];        // aggregated h2 per fp node (fp32)
__device__ float g_es[N_PANO];
__device__ float g_ed[N_PANO];
__device__ float g_es2[N_PANO];
__device__ float g_ed2[N_PANO];
__device__ float g_es3[N_PANO];
__device__ float g_edfp[N_FP];
__device__ float g_wc[704];
// split-bf16 weight images, [N][K] row-major
__device__ ushort_t g_wb0hi[256 * 128], g_wb0lo[256 * 128];
__device__ ushort_t g_wb1hi[256 * 128], g_wb1lo[256 * 128];
__device__ ushort_t g_wbthi[64 * 128],  g_wbtlo[64 * 128];
// CSR build
__device__ int g_cnt[N_PANO];
__device__ int g_off[N_PANO + 1];
__device__ int g_cur[N_PANO];
__device__ int g_srt[E_PP];
__device__ int g_cnt_fp[N_FP];
__device__ int g_off_fp[N_FP + 1];
__device__ int g_cur_fp[N_FP];
__device__ int g_srt_fp[E_PF];
__device__ int g_flagged[SCAN_BLKS];        // aggregate | SCAN_FLAG (decoupled lookback)

// ---------------- helpers ----------------
__device__ __forceinline__ uint32_t smem_u32(const void* p) {
    uint32_t a;
    asm("{ .reg .u64 t; cvta.to.shared.u64 t, %1; cvt.u32.u64 %0, t; }" : "=r"(a) : "l"(p));
    return a;
}
__device__ __forceinline__ void ldsm_x4(uint32_t* r, uint32_t addr) {
    asm volatile("ldmatrix.sync.aligned.m8n8.x4.shared.b16 {%0,%1,%2,%3}, [%4];"
                 : "=r"(r[0]), "=r"(r[1]), "=r"(r[2]), "=r"(r[3]) : "r"(addr));
}
__device__ __forceinline__ void ldsm_x2(uint32_t* r, uint32_t addr) {
    asm volatile("ldmatrix.sync.aligned.m8n8.x2.shared.b16 {%0,%1}, [%2];"
                 : "=r"(r[0]), "=r"(r[1]) : "r"(addr));
}
__device__ __forceinline__ void mma16816(float* d, const uint32_t* a, const uint32_t* b) {
    asm volatile("mma.sync.aligned.m16n8k16.row.col.f32.bf16.bf16.f32 "
                 "{%0,%1,%2,%3}, {%4,%5,%6,%7}, {%8,%9}, {%0,%1,%2,%3};"
                 : "+f"(d[0]), "+f"(d[1]), "+f"(d[2]), "+f"(d[3])
                 : "r"(a[0]), "r"(a[1]), "r"(a[2]), "r"(a[3]), "r"(b[0]), "r"(b[1]));
}
__device__ __forceinline__ void split_bf16(float v, ushort_t& h, ushort_t& l) {
    __nv_bfloat16 hb = __float2bfloat16(v);
    float r = v - __bfloat162float(hb);
    __nv_bfloat16 lb = __float2bfloat16(r);
    memcpy(&h, &hb, 2); memcpy(&l, &lb, 2);
}

// ---------------- GEMM body: fp32 A in, split to bf16 hi/lo in-kernel ----------------
// NT==128: C1h (by==0, fp16) / C2h (by==1, fp16), cstride 128.
// NT==64 with Cf != 0: fp32 output Cf[M,64] += bias.
template<int NT>
__device__ __forceinline__ void gemm_body(
        int bx, int by,
        const float* __restrict__ A,
        const ushort_t* __restrict__ Bhi, const ushort_t* __restrict__ Blo,
        ushort_t* __restrict__ C1h, ushort_t* __restrict__ C2h,
        const float* __restrict__ bias, float* __restrict__ Cf, int M) {
    constexpr int NTW = NT / 4;
    constexpr int NTILES = NTW / 8;
    __shared__ ushort_t As[2][128][40];
    __shared__ ushort_t Bs[2][NT][40];
    const int tid = threadIdx.x;
    const int wid = tid >> 5, lane = tid & 31;
    const int wm = wid >> 2, wn = wid & 3;
    const int m0 = bx * 128;
    const int nb = by * 128;

    float d[4][NTILES][4];
    #pragma unroll
    for (int mt = 0; mt < 4; mt++)
        #pragma unroll
        for (int nt = 0; nt < NTILES; nt++)
            #pragma unroll
            for (int j = 0; j < 4; j++) d[mt][nt][j] = 0.f;

    #pragma unroll 1
    for (int k0 = 0; k0 < 128; k0 += 32) {
        #pragma unroll
        for (int l = 0; l < 4; l++) {
            int i = tid + l * 256;
            int r = i >> 3, cq = (i & 7) * 4;
            float4 v = make_float4(0.f, 0.f, 0.f, 0.f);
            if (m0 + r < M) v = *(const float4*)&A[(size_t)(m0 + r) * 128 + k0 + cq];
            ushort4 h4, l4;
            split_bf16(v.x, h4.x, l4.x); split_bf16(v.y, h4.y, l4.y);
            split_bf16(v.z, h4.z, l4.z); split_bf16(v.w, h4.w, l4.w);
            *(ushort4*)&As[0][r][cq] = h4;
            *(ushort4*)&As[1][r][cq] = l4;
        }
        #pragma unroll
        for (int l = 0; l < (NT * 4) / 256; l++) {
            int i = tid + l * 256;
            int r = i >> 2, s = i & 3;
            *(uint4*)&Bs[0][r][s * 8] = *(const uint4*)&Bhi[(size_t)(nb + r) * 128 + k0 + s * 8];
            *(uint4*)&Bs[1][r][s * 8] = *(const uint4*)&Blo[(size_t)(nb + r) * 128 + k0 + s * 8];
        }
        __syncthreads();
        #pragma unroll
        for (int kk = 0; kk < 32; kk += 16) {
            uint32_t ah[4][4], al[4][4], bh[NTILES][2], bl[NTILES][2];
            #pragma unroll
            for (int mt = 0; mt < 4; mt++) {
                int ar = wm * 64 + mt * 16 + (lane & 15);
                int ac = kk + (lane >> 4) * 8;
                ldsm_x4(ah[mt], smem_u32(&As[0][ar][ac]));
                ldsm_x4(al[mt], smem_u32(&As[1][ar][ac]));
            }
            #pragma unroll
            for (int nt = 0; nt < NTILES; nt++) {
                int l16 = lane & 15;
                int br = wn * NTW + nt * 8 + (l16 & 7);
                int bc = kk + (l16 >> 3) * 8;
                ldsm_x2(bh[nt], smem_u32(&Bs[0][br][bc]));
                ldsm_x2(bl[nt], smem_u32(&Bs[1][br][bc]));
            }
            #pragma unroll
            for (int mt = 0; mt < 4; mt++)
                #pragma unroll
                for (int nt = 0; nt < NTILES; nt++) {
                    mma16816(d[mt][nt], ah[mt], bh[nt]);
                    mma16816(d[mt][nt], al[mt], bh[nt]);
                    mma16816(d[mt][nt], ah[mt], bl[nt]);
                }
        }
        __syncthreads();
    }
    if (NT == 64 && Cf) {
        // fp32 output with bias (translate final)
        #pragma unroll
        for (int mt = 0; mt < 4; mt++) {
            int r0 = m0 + wm * 64 + mt * 16 + (lane >> 2);
            #pragma unroll
            for (int nt = 0; nt < NTILES; nt++) {
                int c = wn * NTW + nt * 8 + (lane & 3) * 2;
                float b0 = __ldg(&bias[c]), b1 = __ldg(&bias[c + 1]);
                if (r0 < M)
                    *(float2*)&Cf[(size_t)r0 * 64 + c] = make_float2(d[mt][nt][0] + b0,
                                                                     d[mt][nt][1] + b1);
                if (r0 + 8 < M)
                    *(float2*)&Cf[(size_t)(r0 + 8) * 64 + c] = make_float2(d[mt][nt][2] + b0,
                                                                           d[mt][nt][3] + b1);
            }
        }
        return;
    }
    ushort_t* C = (NT == 64 || by == 0) ? C1h : C2h;
    const int cstride = (NT == 64) ? 64 : 128;
    #pragma unroll
    for (int mt = 0; mt < 4; mt++) {
        int r0 = m0 + wm * 64 + mt * 16 + (lane >> 2);
        #pragma unroll
        for (int nt = 0; nt < NTILES; nt++) {
            int c = wn * NTW + nt * 8 + (lane & 3) * 2;
            if (r0 < M)
                *reinterpret_cast<__half2*>(&C[(size_t)r0 * cstride + c]) =
                    __floats2half2_rn(d[mt][nt][0], d[mt][nt][1]);
            if (r0 + 8 < M)
                *reinterpret_cast<__half2*>(&C[(size_t)(r0 + 8) * cstride + c]) =
                    __floats2half2_rn(d[mt][nt][2], d[mt][nt][3]);
        }
    }
}

template<int NT>
__global__ void __launch_bounds__(256) mmagemm_kernel(
        const float* __restrict__ A,
        const ushort_t* __restrict__ Bhi, const ushort_t* __restrict__ Blo,
        ushort_t* __restrict__ C1h, ushort_t* __restrict__ C2h,
        const float* __restrict__ bias, float* __restrict__ Cf, int M) {
    gemm_body<NT>(blockIdx.x, blockIdx.y, A, Bhi, Blo, C1h, C2h, bias, Cf, M);
}

// ---------------- K1: weight prep + compose + zero counters/flags ----------------
__global__ void __launch_bounds__(256) prep_all_kernel(
        const float* __restrict__ Ws0, const float* __restrict__ as0,
        const float* __restrict__ Wd0, const float* __restrict__ ad0,
        const float* __restrict__ Lw0,
        const float* __restrict__ Ws1, const float* __restrict__ as1,
        const float* __restrict__ Wd1, const float* __restrict__ ad1,
        const float* __restrict__ Lw1,
        const float* __restrict__ Wts, const float* __restrict__ ats,
        const float* __restrict__ Wtd, const float* __restrict__ atd) {
    int blk = blockIdx.x;
    int t = threadIdx.x;
    if (blk < 288) {
        int idx = blk * 256 + t;
        ushort_t *ih, *il;
        int n, k;
        float v;
        if (idx < 32768) {
            n = idx >> 7; k = idx & 127;
            v = (n < 128) ? Ws0[k * 128 + n] : Lw0[k * 128 + (n - 128)];
            ih = g_wb0hi; il = g_wb0lo;
        } else if (idx < 65536) {
            int e = idx - 32768;
            n = e >> 7; k = e & 127;
            v = (n < 128) ? Ws1[k * 128 + n] : Lw1[k * 128 + (n - 128)];
            ih = g_wb1hi; il = g_wb1lo;
        } else {
            int e = idx - 65536;
            n = e >> 7; k = e & 127;
            v = Wts[k * 64 + n];
            ih = g_wbthi; il = g_wbtlo;
        }
        ushort_t h, l;
        split_bf16(v, h, l);
        ih[n * 128 + k] = h;
        il[n * 128 + k] = l;
    } else if (blk < 291) {
        int b = blk - 288;
        if (b == 0) {
            if (t < 128) {
                float s = 0.f;
                for (int n = 0; n < 128; n++) s += Ws0[t * 128 + n] * as0[n];
                g_wc[t] = s;
            } else {
                int i = t - 128; float s = 0.f;
                for (int n = 0; n < 128; n++) s += Wd0[i * 128 + n] * ad0[n];
                g_wc[128 + i] = s;
            }
        } else if (b == 1) {
            if (t < 128) {
                float s = 0.f;
                for (int n = 0; n < 128; n++) s += Ws1[t * 128 + n] * as1[n];
                g_wc[256 + t] = s;
            } else {
                int i = t - 128; float s = 0.f;
                for (int n = 0; n < 128; n++) s += Wd1[i * 128 + n] * ad1[n];
                g_wc[384 + i] = s;
            }
        } else {
            if (t < 128) {
                float s = 0.f;
                for (int n = 0; n < 64; n++) s += Wts[t * 64 + n] * ats[n];
                g_wc[512 + t] = s;
            } else if (t < 192) {
                int i = t - 128; float s = 0.f;
                for (int n = 0; n < 64; n++) s += Wtd[i * 64 + n] * atd[n];
                g_wc[640 + i] = s;
            }
        }
    } else {
        int i = (blk - 291) * 256 + t;
        if (i < N_PANO) g_cnt[i] = 0;
        else if (i < N_PANO + N_FP) g_cnt_fp[i - N_PANO] = 0;
        else if (i < N_PANO + N_FP + SCAN_BLKS) g_flagged[i - N_PANO - N_FP] = 0;
    }
}

// ---------------- K2: vectorized histogram + attention dot GEMVs ----------------
#define K2_HPP   782
#define K2_HIST  (K2_HPP + 49)
#define K2_GEMV2 (K2_HIST + 6250)
#define K2_TOTAL (K2_GEMV2 + 1250)
__global__ void __launch_bounds__(256) hist_gemv_kernel(
        const int* __restrict__ dst_pp, const int* __restrict__ dst_pf,
        const float* __restrict__ X, const float* __restrict__ Xfp) {
    int blk = blockIdx.x;
    int t = threadIdx.x;
    if (blk < K2_HPP) {
        int g = blk * 256 + t;
        if (g * 4 < E_PP) {
            int4 d = *(const int4*)&dst_pp[g * 4];
            atomicAdd(&g_cnt[d.x], 1);
            atomicAdd(&g_cnt[d.y], 1);
            atomicAdd(&g_cnt[d.z], 1);
            atomicAdd(&g_cnt[d.w], 1);
        }
    } else if (blk < K2_HIST) {
        int g = (blk - K2_HPP) * 256 + t;
        if (g * 4 < E_PF) {
            int4 d = *(const int4*)&dst_pf[g * 4];
            atomicAdd(&g_cnt_fp[d.x], 1);
            atomicAdd(&g_cnt_fp[d.y], 1);
            atomicAdd(&g_cnt_fp[d.z], 1);
            atomicAdd(&g_cnt_fp[d.w], 1);
        }
    } else if (blk < K2_GEMV2) {
        int gw = ((blk - K2_HIST) * 256 + t) >> 5;
        int lane = t & 31;
        if (gw >= N_PANO) return;
        float4 x = *(const float4*)&X[(size_t)gw * 128 + lane * 4];
        float4 a = *(const float4*)&g_wc[0 + lane * 4];
        float4 b = *(const float4*)&g_wc[128 + lane * 4];
        float sa = x.x * a.x + x.y * a.y + x.z * a.z + x.w * a.w;
        float sb = x.x * b.x + x.y * b.y + x.z * b.z + x.w * b.w;
        #pragma unroll
        for (int o = 16; o; o >>= 1) {
            sa += __shfl_xor_sync(0xFFFFFFFFu, sa, o);
            sb += __shfl_xor_sync(0xFFFFFFFFu, sb, o);
        }
        if (lane == 0) { g_es[gw] = sa; g_ed[gw] = sb; }
    } else {
        int gw = ((blk - K2_GEMV2) * 256 + t) >> 5;
        int lane = t & 31;
        if (gw >= N_FP) return;
        float2 x = *(const float2*)&Xfp[(size_t)gw * 64 + lane * 2];
        float2 a = *(const float2*)&g_wc[640 + lane * 2];
        float s = x.x * a.x + x.y * a.y;
        #pragma unroll
        for (int o = 16; o; o >>= 1) s += __shfl_xor_sync(0xFFFFFFFFu, s, o);
        if (lane == 0) g_edfp[gw] = s;
    }
}

// ---- K3: fused scan (tile scan + decoupled lookback + offset add) ----
__global__ void __launch_bounds__(256) scan_fused_kernel() {
    __shared__ int woff[9];
    __shared__ int s_bo;
    __shared__ int s_tot;
    int blk = blockIdx.x;
    bool fp = blk >= SCAN_BPP;
    const int N = fp ? N_FP : N_PANO;
    const int* cnt = fp ? g_cnt_fp : g_cnt;
    int* off = fp ? g_off_fp : g_off;
    int* cur = fp ? g_cur_fp : g_cur;
    int seg0 = fp ? SCAN_BPP : 0;
    int segN = fp ? SCAN_BLKS : SCAN_BPP;
    int base = (fp ? blk - SCAN_BPP : blk) * 1024;
    int t = threadIdx.x;
    int lane = t & 31, wid = t >> 5;
    int idx = base + t * 4;
    int4 v = make_int4(0, 0, 0, 0);
    if (idx < N) v = *(const int4*)&cnt[idx];
    int s0 = v.x, s1 = v.x + v.y, s2 = s1 + v.z, tot = s2 + v.w;
    int inc = tot;
    #pragma unroll
    for (int o = 1; o < 32; o <<= 1) {
        int n = __shfl_up_sync(0xFFFFFFFFu, inc, o);
        if (lane >= o) inc += n;
    }
    if (lane == 31) woff[wid] = inc;
    __syncthreads();
    if (t == 0) {
        int run = 0;
        #pragma unroll
        for (int j = 0; j < 8; j++) { int x = woff[j]; woff[j] = run; run += x; }
        s_tot = run;
        atomicExch(&g_flagged[blk], run | SCAN_FLAG);
        s_bo = 0;
    }
    __syncthreads();
    if (t < blk - seg0) {
        int j = seg0 + t;
        int w;
        do { w = atomicAdd(&g_flagged[j], 0); } while (!(w & SCAN_FLAG));
        atomicAdd(&s_bo, w & (SCAN_FLAG - 1));
    }
    __syncthreads();
    int bo = s_bo;
    if (t == 0 && blk == segN - 1) off[N] = bo + s_tot;
    int exc = bo + woff[wid] + inc - tot;
    if (idx < N) {
        int4 o = make_int4(exc, exc + s0, exc + s1, exc + s2);
        *(int4*)&off[idx] = o;
        *(int4*)&cur[idx] = o;
    }
}

// ---------------- K4: layer-0 GEMM fused with edge scatter ----------------
__global__ void __launch_bounds__(256) gemm0_scatter_kernel(
        const float* __restrict__ A,
        const ushort_t* __restrict__ Bhi, const ushort_t* __restrict__ Blo,
        ushort_t* __restrict__ C1h, ushort_t* __restrict__ C2h,
        const int* __restrict__ src_pp, const int* __restrict__ dst_pp,
        const int* __restrict__ src_pf, const int* __restrict__ dst_pf) {
    int blk = blockIdx.x;
    if (blk < 2 * GEMM_MBLKS) {
        gemm_body<128>(blk % GEMM_MBLKS, blk / GEMM_MBLKS, A, Bhi, Blo, C1h, C2h,
                       (const float*)0, (float*)0, N_PANO);
    } else {
        int i = (blk - 2 * GEMM_MBLKS) * 256 + threadIdx.x;
        if (i < E_PP) {
            int pos = atomicAdd(&g_cur[dst_pp[i]], 1);
            g_srt[pos] = src_pp[i];
        } else if (i < E_PP + E_PF) {
            int j = i - E_PP;
            int pos = atomicAdd(&g_cur_fp[dst_pf[j]], 1);
            g_srt_fp[pos] = src_pf[j];
        }
    }
}

// ---------------- CSR aggregation + finalize + next-stage dots ----------------
// hout == 0: write h fp32 to g_h (feeds next GEMM).  hout != 0: write h fp16 to hout.
__global__ void __launch_bounds__(256) agg_pp_kernel(const float* __restrict__ b,
                                                     const float* __restrict__ Lb,
                                                     const float* __restrict__ es_in,
                                                     const float* __restrict__ ed_in,
                                                     const float* __restrict__ wa,
                                                     const float* __restrict__ wb,
                                                     float* __restrict__ ea,
                                                     float* __restrict__ eb,
                                                     ushort_t* __restrict__ hout) {
    int gw = (blockIdx.x * blockDim.x + threadIdx.x) >> 5;
    int lane = threadIdx.x & 31;
    if (gw >= N_PANO) return;
    int start = g_off[gw];
    int end   = g_off[gw + 1];
    float edd = ed_in[gw];
    float4 acc = make_float4(0.f, 0.f, 0.f, 0.f);
    float exsum = 0.f;
    for (int base = start; base < end; base += 32) {
        int m = end - base; if (m > 32) m = 32;
        int s = 0; float ex = 0.f;
        if (lane < m) {
            s = g_srt[base + lane];
            float ez = es_in[s] + edd;
            float e = ez > 0.f ? ez : 0.2f * ez;
            ex = __expf(e);
        }
        exsum += ex;
        for (int j = 0; j < m; j++) {
            int sj   = __shfl_sync(0xFFFFFFFFu, s, j);
            float xj = __shfl_sync(0xFFFFFFFFu, ex, j);
            uint2 hp = *(const uint2*)&g_hsh[(size_t)sj * 128 + lane * 4];
            float2 f0 = __half22float2(*reinterpret_cast<const __half2*>(&hp.x));
            float2 f1 = __half22float2(*reinterpret_cast<const __half2*>(&hp.y));
            acc.x += f0.x * xj; acc.y += f0.y * xj;
            acc.z += f1.x * xj; acc.w += f1.y * xj;
        }
    }
    #pragma unroll
    for (int o = 16; o; o >>= 1) exsum += __shfl_xor_sync(0xFFFFFFFFu, exsum, o);
    float inv = exsum > 0.f ? 1.f / exsum : 0.f;
    uint2 lp = *(const uint2*)&g_linh[(size_t)gw * 128 + lane * 4];
    float2 l0 = __half22float2(*reinterpret_cast<const __half2*>(&lp.x));
    float2 l1 = __half22float2(*reinterpret_cast<const __half2*>(&lp.y));
    float4 bb = *(const float4*)&b[lane * 4];
    float4 lb = *(const float4*)&Lb[lane * 4];
    float4 r;
    r.x = fmaxf(acc.x * inv + bb.x + l0.x + lb.x, 0.f);
    r.y = fmaxf(acc.y * inv + bb.y + l0.y + lb.y, 0.f);
    r.z = fmaxf(acc.z * inv + bb.z + l1.x + lb.z, 0.f);
    r.w = fmaxf(acc.w * inv + bb.w + l1.y + lb.w, 0.f);
    if (hout) {
        __half2 p0 = __floats2half2_rn(r.x, r.y);
        __half2 p1 = __floats2half2_rn(r.z, r.w);
        uint2 u;
        memcpy(&u.x, &p0, 4); memcpy(&u.y, &p1, 4);
        *(uint2*)&hout[(size_t)gw * 128 + lane * 4] = u;
    } else {
        *(float4*)&g_h[(size_t)gw * 128 + lane * 4] = r;
    }
    float4 a4 = *(const float4*)&wa[lane * 4];
    float sa = r.x * a4.x + r.y * a4.y + r.z * a4.z + r.w * a4.w;
    float sb = 0.f;
    if (eb) {
        float4 b4 = *(const float4*)&wb[lane * 4];
        sb = r.x * b4.x + r.y * b4.y + r.z * b4.z + r.w * b4.w;
    }
    #pragma unroll
    for (int o = 16; o; o >>= 1) {
        sa += __shfl_xor_sync(0xFFFFFFFFu, sa, o);
        sb += __shfl_xor_sync(0xFFFFFFFFu, sb, o);
    }
    if (lane == 0) {
        ea[gw] = sa;
        if (eb) eb[gw] = sb;
    }
}

// ---------------- agg_pf: aggregate h2 (128-wide fp16) -> c[N_FP,128] fp32 ----------------
__global__ void __launch_bounds__(256) agg_pf_kernel() {
    int gw = (blockIdx.x * blockDim.x + threadIdx.x) >> 5;
    int lane = threadIdx.x & 31;
    if (gw >= N_FP) return;
    int start = g_off_fp[gw];
    int end   = g_off_fp[gw + 1];
    float edd = g_edfp[gw];
    float4 acc = make_float4(0.f, 0.f, 0.f, 0.f);
    float exsum = 0.f;
    for (int base = start; base < end; base += 32) {
        int m = end - base; if (m > 32) m = 32;
        int s = 0; float ex = 0.f;
        if (lane < m) {
            s = g_srt_fp[base + lane];
            float ez = g_es3[s] + edd;
            float e = ez > 0.f ? ez : 0.2f * ez;
            ex = __expf(e);
        }
        exsum += ex;
        for (int j = 0; j < m; j++) {
            int sj   = __shfl_sync(0xFFFFFFFFu, s, j);
            float xj = __shfl_sync(0xFFFFFFFFu, ex, j);
            uint2 hp = *(const uint2*)&g_h2h[(size_t)sj * 128 + lane * 4];
            float2 f0 = __half22float2(*reinterpret_cast<const __half2*>(&hp.x));
            float2 f1 = __half22float2(*reinterpret_cast<const __half2*>(&hp.y));
            acc.x += f0.x * xj; acc.y += f0.y * xj;
            acc.z += f1.x * xj; acc.w += f1.y * xj;
        }
    }
    #pragma unroll
    for (int o = 16; o; o >>= 1) exsum += __shfl_xor_sync(0xFFFFFFFFu, exsum, o);
    float inv = exsum > 0.f ? 1.f / exsum : 0.f;
    *(float4*)&g_c[(size_t)gw * 128 + lane * 4] =
        make_float4(acc.x * inv, acc.y * inv, acc.z * inv, acc.w * inv);
}

// ---------------- launch ----------------
extern "C" void kernel_launch(void* const* d_in, const int* in_sizes, int n_in,
                              void* d_out, int out_size) {
    const float* x_pano = (const float*)d_in[0];
    const float* x_fp   = (const float*)d_in[1];
    const float* Ws0 = (const float*)d_in[2];
    const float* Wd0 = (const float*)d_in[3];
    const float* as0 = (const float*)d_in[4];
    const float* ad0 = (const float*)d_in[5];
    const float* b0  = (const float*)d_in[6];
    const float* Lw0 = (const float*)d_in[7];
    const float* Lb0 = (const float*)d_in[8];
    const float* Ws1 = (const float*)d_in[9];
    const float* Wd1 = (const float*)d_in[10];
    const float* as1 = (const float*)d_in[11];
    const float* ad1 = (const float*)d_in[12];
    const float* b1  = (const float*)d_in[13];
    const float* Lw1 = (const float*)d_in[14];
    const float* Lb1 = (const float*)d_in[15];
    const float* Wts = (const float*)d_in[16];
    const float* Wtd = (const float*)d_in[17];
    const float* ats = (const float*)d_in[18];
    const float* atd = (const float*)d_in[19];
    const float* bt  = (const float*)d_in[20];
    const int* edge_pp = (const int*)d_in[21];
    const int* pf_src  = (const int*)d_in[22];
    const int* pf_dst  = (const int*)d_in[23];
    const int* pp_src = edge_pp;
    const int* pp_dst = edge_pp + E_PP;

    float *p_h, *p_c, *p_es, *p_ed, *p_es2, *p_ed2, *p_es3, *p_wc;
    cudaGetSymbolAddress((void**)&p_h,    g_h);
    cudaGetSymbolAddress((void**)&p_c,    g_c);
    cudaGetSymbolAddress((void**)&p_es,   g_es);
    cudaGetSymbolAddress((void**)&p_ed,   g_ed);
    cudaGetSymbolAddress((void**)&p_es2,  g_es2);
    cudaGetSymbolAddress((void**)&p_ed2,  g_ed2);
    cudaGetSymbolAddress((void**)&p_es3,  g_es3);
    cudaGetSymbolAddress((void**)&p_wc,   g_wc);
    ushort_t *p_hsh, *p_h2h, *p_linh;
    ushort_t *p_b0hi, *p_b0lo, *p_b1hi, *p_b1lo, *p_bthi, *p_btlo;
    cudaGetSymbolAddress((void**)&p_hsh,  g_hsh);
    cudaGetSymbolAddress((void**)&p_h2h,  g_h2h);
    cudaGetSymbolAddress((void**)&p_linh, g_linh);
    cudaGetSymbolAddress((void**)&p_b0hi, g_wb0hi);
    cudaGetSymbolAddress((void**)&p_b0lo, g_wb0lo);
    cudaGetSymbolAddress((void**)&p_b1hi, g_wb1hi);
    cudaGetSymbolAddress((void**)&p_b1lo, g_wb1lo);
    cudaGetSymbolAddress((void**)&p_bthi, g_wbthi);
    cudaGetSymbolAddress((void**)&p_btlo, g_wbtlo);

    // K1: weight prep + compose + zero counters/flags
    prep_all_kernel<<<527, 256>>>(Ws0, as0, Wd0, ad0, Lw0,
                                  Ws1, as1, Wd1, ad1, Lw1,
                                  Wts, ats, Wtd, atd);
    // K2: vectorized histogram + attention dots
    hist_gemv_kernel<<<K2_TOTAL, 256>>>(pp_dst, pf_dst, x_pano, x_fp);
    // K3: fused scan (decoupled lookback)
    scan_fused_kernel<<<SCAN_BLKS, 256>>>();
    // K4: layer-0 GEMM + edge scatter (overlapped)
    gemm0_scatter_kernel<<<2 * GEMM_MBLKS + EALL_BLKS, 256>>>(
        x_pano, p_b0hi, p_b0lo, p_hsh, p_linh,
        pp_src, pp_dst, pf_src, pf_dst);
    // layer 0 aggregation -> h1 (fp32) + layer-1 attention dots
    agg_pp_kernel<<<6250, 256>>>(b0, Lb0, p_es, p_ed, p_wc + 256, p_wc + 384,
                                 p_es2, p_ed2, (ushort_t*)0);
    // layer 1 GEMM
    mmagemm_kernel<128><<<dim3(GEMM_MBLKS, 2), 256>>>(p_h, p_b1hi, p_b1lo, p_hsh, p_linh,
                                                      (const float*)0, (float*)0, N_PANO);
    // layer 1 aggregation -> h2 (fp16 payload) + translate attention dots
    agg_pp_kernel<<<6250, 256>>>(b1, Lb1, p_es2, p_ed2, p_wc + 512, (const float*)0,
                                 p_es3, (float*)0, p_h2h);
    // translate: aggregate-then-project (exact: GEMM distributes over convex combo)
    agg_pf_kernel<<<1250, 256>>>();
    mmagemm_kernel<64><<<dim3(FP_MBLKS, 1), 256>>>(p_c, p_bthi, p_btlo,
                                                   (ushort_t*)0, (ushort_t*)0,
                                                   bt, (float*)d_out, N_FP);
}

// round 14
// speedup vs baseline: 1.1566x; 1.0714x over previous
#include <cuda_runtime.h>
#include <cuda_bf16.h>
#include <cuda_fp16.h>
#include <math.h>
#include <stdint.h>
#include <string.h>

#define N_PANO 50000
#define N_FP   10000
#define HID    128
#define E_PP   800000
#define E_PF   50000

#define SCAN_BPP 49
#define SCAN_BFP 10
#define SCAN_BLKS (SCAN_BPP + SCAN_BFP)
#define SCAN_FLAG (1 << 30)

#define GEMM_MBLKS 391        // ceil(50000/128)
#define FP_MBLKS   79         // ceil(10000/128)
#define EALL_BLKS  3321       // ceil(850000/256)

typedef unsigned short ushort_t;

// ---------------- device scratch (static, no allocation; zero-init guaranteed) ----------------
__device__ float    g_h[N_PANO * HID];      // fp32 activations (GEMM A input)
__device__ ushort_t g_hsh[N_PANO * HID];    // hs fp16 (gather payload)
__device__ ushort_t g_h2h[N_PANO * HID];    // h2 fp16 (translate gather payload)
__device__ ushort_t g_linh[N_PANO * HID];   // lin fp16
__device__ float    g_c[N_FP * 128];        // aggregated h2 per fp node (fp32)
__device__ float g_es[N_PANO];
__device__ float g_ed[N_PANO];
__device__ float g_es2[N_PANO];
__device__ float g_ed2[N_PANO];
__device__ float g_es3[N_PANO];
__device__ float g_edfp[N_FP];
__device__ float g_wc[704];
// fp16 weight images, [N][K] row-major (single image per matrix)
__device__ ushort_t g_wb0[256 * 128];
__device__ ushort_t g_wb1[256 * 128];
__device__ ushort_t g_wbt[64 * 128];
// CSR build (zero-init at load; re-zeroed by final kernel each launch)
__device__ int g_cnt[N_PANO];
__device__ int g_off[N_PANO + 1];
__device__ int g_cur[N_PANO];
__device__ int g_srt[E_PP];
__device__ int g_cnt_fp[N_FP];
__device__ int g_off_fp[N_FP + 1];
__device__ int g_cur_fp[N_FP];
__device__ int g_srt_fp[E_PF];
__device__ int g_flagged[SCAN_BLKS];

// ---------------- helpers ----------------
__device__ __forceinline__ uint32_t smem_u32(const void* p) {
    uint32_t a;
    asm("{ .reg .u64 t; cvta.to.shared.u64 t, %1; cvt.u32.u64 %0, t; }" : "=r"(a) : "l"(p));
    return a;
}
__device__ __forceinline__ void ldsm_x4(uint32_t* r, uint32_t addr) {
    asm volatile("ldmatrix.sync.aligned.m8n8.x4.shared.b16 {%0,%1,%2,%3}, [%4];"
                 : "=r"(r[0]), "=r"(r[1]), "=r"(r[2]), "=r"(r[3]) : "r"(addr));
}
__device__ __forceinline__ void ldsm_x2(uint32_t* r, uint32_t addr) {
    asm volatile("ldmatrix.sync.aligned.m8n8.x2.shared.b16 {%0,%1}, [%2];"
                 : "=r"(r[0]), "=r"(r[1]) : "r"(addr));
}
__device__ __forceinline__ void mma16816f(float* d, const uint32_t* a, const uint32_t* b) {
    asm volatile("mma.sync.aligned.m16n8k16.row.col.f32.f16.f16.f32 "
                 "{%0,%1,%2,%3}, {%4,%5,%6,%7}, {%8,%9}, {%0,%1,%2,%3};"
                 : "+f"(d[0]), "+f"(d[1]), "+f"(d[2]), "+f"(d[3])
                 : "r"(a[0]), "r"(a[1]), "r"(a[2]), "r"(a[3]), "r"(b[0]), "r"(b[1]));
}
__device__ __forceinline__ void split_f16(float v, ushort_t& h, ushort_t& l) {
    __half hb = __float2half_rn(v);
    float r = v - __half2float(hb);
    __half lb = __float2half_rn(r);
    memcpy(&h, &hb, 2); memcpy(&l, &lb, 2);
}

// ---------------- GEMM body: fp32 A in, split to fp16 hi/lo; B single fp16; 2 terms ----------------
// NT==128: C1h (by==0) / C2h (by==1) fp16 outputs, stride 128.
// NT==64 with Cf != 0: fp32 output Cf[M,64] + bias (translate final).
template<int NT>
__device__ __forceinline__ void gemm_body(
        int bx, int by,
        const float* __restrict__ A,
        const ushort_t* __restrict__ B,
        ushort_t* __restrict__ C1h, ushort_t* __restrict__ C2h,
        const float* __restrict__ bias, float* __restrict__ Cf, int M) {
    constexpr int NTW = NT / 4;
    constexpr int NTILES = NTW / 8;
    __shared__ ushort_t As[2][128][40];
    __shared__ ushort_t Bs[NT][40];
    const int tid = threadIdx.x;
    const int wid = tid >> 5, lane = tid & 31;
    const int wm = wid >> 2, wn = wid & 3;
    const int m0 = bx * 128;
    const int nb = by * 128;

    float d[4][NTILES][4];
    #pragma unroll
    for (int mt = 0; mt < 4; mt++)
        #pragma unroll
        for (int nt = 0; nt < NTILES; nt++)
            #pragma unroll
            for (int j = 0; j < 4; j++) d[mt][nt][j] = 0.f;

    #pragma unroll 1
    for (int k0 = 0; k0 < 128; k0 += 32) {
        // A tile: fp32 load, split fp16 hi/lo in regs, store to SMEM
        #pragma unroll
        for (int l = 0; l < 4; l++) {
            int i = tid + l * 256;
            int r = i >> 3, cq = (i & 7) * 4;
            float4 v = make_float4(0.f, 0.f, 0.f, 0.f);
            if (m0 + r < M) v = *(const float4*)&A[(size_t)(m0 + r) * 128 + k0 + cq];
            ushort4 h4, l4;
            split_f16(v.x, h4.x, l4.x); split_f16(v.y, h4.y, l4.y);
            split_f16(v.z, h4.z, l4.z); split_f16(v.w, h4.w, l4.w);
            *(ushort4*)&As[0][r][cq] = h4;
            *(ushort4*)&As[1][r][cq] = l4;
        }
        // B tile: single fp16 image, NT rows x 32 halves = NT*4 16B-chunks
        #pragma unroll
        for (int l = 0; l < (NT * 4) / 256; l++) {
            int c = tid + l * 256;
            int r = c >> 2, q = c & 3;
            *(uint4*)&Bs[r][q * 8] = *(const uint4*)&B[(size_t)(nb + r) * 128 + k0 + q * 8];
        }
        __syncthreads();
        #pragma unroll
        for (int kk = 0; kk < 32; kk += 16) {
            uint32_t ah[4][4], al[4][4], bh[NTILES][2];
            #pragma unroll
            for (int mt = 0; mt < 4; mt++) {
                int ar = wm * 64 + mt * 16 + (lane & 15);
                int ac = kk + (lane >> 4) * 8;
                ldsm_x4(ah[mt], smem_u32(&As[0][ar][ac]));
                ldsm_x4(al[mt], smem_u32(&As[1][ar][ac]));
            }
            #pragma unroll
            for (int nt = 0; nt < NTILES; nt++) {
                int l16 = lane & 15;
                int br = wn * NTW + nt * 8 + (l16 & 7);
                int bc = kk + (l16 >> 3) * 8;
                ldsm_x2(bh[nt], smem_u32(&Bs[br][bc]));
            }
            #pragma unroll
            for (int mt = 0; mt < 4; mt++)
                #pragma unroll
                for (int nt = 0; nt < NTILES; nt++) {
                    mma16816f(d[mt][nt], ah[mt], bh[nt]);
                    mma16816f(d[mt][nt], al[mt], bh[nt]);
                }
        }
        __syncthreads();
    }
    if (NT == 64 && Cf) {
        #pragma unroll
        for (int mt = 0; mt < 4; mt++) {
            int r0 = m0 + wm * 64 + mt * 16 + (lane >> 2);
            #pragma unroll
            for (int nt = 0; nt < NTILES; nt++) {
                int c = wn * NTW + nt * 8 + (lane & 3) * 2;
                float b0 = __ldg(&bias[c]), b1 = __ldg(&bias[c + 1]);
                if (r0 < M)
                    *(float2*)&Cf[(size_t)r0 * 64 + c] = make_float2(d[mt][nt][0] + b0,
                                                                     d[mt][nt][1] + b1);
                if (r0 + 8 < M)
                    *(float2*)&Cf[(size_t)(r0 + 8) * 64 + c] = make_float2(d[mt][nt][2] + b0,
                                                                           d[mt][nt][3] + b1);
            }
        }
        return;
    }
    ushort_t* C = (NT == 64 || by == 0) ? C1h : C2h;
    const int cstride = (NT == 64) ? 64 : 128;
    #pragma unroll
    for (int mt = 0; mt < 4; mt++) {
        int r0 = m0 + wm * 64 + mt * 16 + (lane >> 2);
        #pragma unroll
        for (int nt = 0; nt < NTILES; nt++) {
            int c = wn * NTW + nt * 8 + (lane & 3) * 2;
            if (r0 < M)
                *reinterpret_cast<__half2*>(&C[(size_t)r0 * cstride + c]) =
                    __floats2half2_rn(d[mt][nt][0], d[mt][nt][1]);
            if (r0 + 8 < M)
                *reinterpret_cast<__half2*>(&C[(size_t)(r0 + 8) * cstride + c]) =
                    __floats2half2_rn(d[mt][nt][2], d[mt][nt][3]);
        }
    }
}

template<int NT>
__global__ void __launch_bounds__(256) mmagemm_kernel(
        const float* __restrict__ A, const ushort_t* __restrict__ B,
        ushort_t* __restrict__ C1h, ushort_t* __restrict__ C2h, int M) {
    gemm_body<NT>(blockIdx.x, blockIdx.y, A, B, C1h, C2h, (const float*)0, (float*)0, M);
}

// ---------------- K1: weight prep (fp16) + compose + histogram ----------------
// g_cnt / g_cnt_fp are guaranteed zero on entry (static init on first call,
// re-zeroed by the final kernel of every launch thereafter).
#define K1_W     288
#define K1_COMP  (K1_W + 3)                 // 291
#define K1_HPP   (K1_COMP + 782)            // 1073
#define K1_TOTAL (K1_HPP + 49)              // 1122
__global__ void __launch_bounds__(256) prep_hist_kernel(
        const float* __restrict__ Ws0, const float* __restrict__ as0,
        const float* __restrict__ Wd0, const float* __restrict__ ad0,
        const float* __restrict__ Lw0,
        const float* __restrict__ Ws1, const float* __restrict__ as1,
        const float* __restrict__ Wd1, const float* __restrict__ ad1,
        const float* __restrict__ Lw1,
        const float* __restrict__ Wts, const float* __restrict__ ats,
        const float* __restrict__ Wtd, const float* __restrict__ atd,
        const int* __restrict__ dst_pp, const int* __restrict__ dst_pf) {
    int blk = blockIdx.x;
    int t = threadIdx.x;
    if (blk < K1_W) {
        int idx = blk * 256 + t;
        ushort_t* img;
        int n, k;
        float v;
        if (idx < 32768) {
            n = idx >> 7; k = idx & 127;
            v = (n < 128) ? Ws0[k * 128 + n] : Lw0[k * 128 + (n - 128)];
            img = g_wb0;
        } else if (idx < 65536) {
            int e = idx - 32768;
            n = e >> 7; k = e & 127;
            v = (n < 128) ? Ws1[k * 128 + n] : Lw1[k * 128 + (n - 128)];
            img = g_wb1;
        } else {
            int e = idx - 65536;
            n = e >> 7; k = e & 127;
            v = Wts[k * 64 + n];
            img = g_wbt;
        }
        __half hv = __float2half_rn(v);
        ushort_t u; memcpy(&u, &hv, 2);
        img[n * 128 + k] = u;
    } else if (blk < K1_COMP) {
        int b = blk - K1_W;
        if (b == 0) {
            if (t < 128) {
                float s = 0.f;
                for (int n = 0; n < 128; n++) s += Ws0[t * 128 + n] * as0[n];
                g_wc[t] = s;
            } else {
                int i = t - 128; float s = 0.f;
                for (int n = 0; n < 128; n++) s += Wd0[i * 128 + n] * ad0[n];
                g_wc[128 + i] = s;
            }
        } else if (b == 1) {
            if (t < 128) {
                float s = 0.f;
                for (int n = 0; n < 128; n++) s += Ws1[t * 128 + n] * as1[n];
                g_wc[256 + t] = s;
            } else {
                int i = t - 128; float s = 0.f;
                for (int n = 0; n < 128; n++) s += Wd1[i * 128 + n] * ad1[n];
                g_wc[384 + i] = s;
            }
        } else {
            if (t < 128) {
                float s = 0.f;
                for (int n = 0; n < 64; n++) s += Wts[t * 64 + n] * ats[n];
                g_wc[512 + t] = s;
            } else if (t < 192) {
                int i = t - 128; float s = 0.f;
                for (int n = 0; n < 64; n++) s += Wtd[i * 64 + n] * atd[n];
                g_wc[640 + i] = s;
            }
        }
    } else if (blk < K1_HPP) {
        int g = (blk - K1_COMP) * 256 + t;
        if (g * 4 < E_PP) {
            int4 d = *(const int4*)&dst_pp[g * 4];
            atomicAdd(&g_cnt[d.x], 1);
            atomicAdd(&g_cnt[d.y], 1);
            atomicAdd(&g_cnt[d.z], 1);
            atomicAdd(&g_cnt[d.w], 1);
        }
    } else {
        int g = (blk - K1_HPP) * 256 + t;
        if (g * 4 < E_PF) {
            int4 d = *(const int4*)&dst_pf[g * 4];
            atomicAdd(&g_cnt_fp[d.x], 1);
            atomicAdd(&g_cnt_fp[d.y], 1);
            atomicAdd(&g_cnt_fp[d.z], 1);
            atomicAdd(&g_cnt_fp[d.w], 1);
        }
    }
}

// ---------------- K2: fused scan (blocks [0,59)) + attention dot GEMVs ----------------
#define K2_GEMV2 (SCAN_BLKS + 6250)        // 6309
#define K2_TOTAL (K2_GEMV2 + 1250)         // 7559
__global__ void __launch_bounds__(256) scan_gemv_kernel(
        const float* __restrict__ X, const float* __restrict__ Xfp) {
    int blk = blockIdx.x;
    int t = threadIdx.x;
    if (blk < SCAN_BLKS) {
        __shared__ int woff[9];
        __shared__ int s_bo;
        __shared__ int s_tot;
        bool fp = blk >= SCAN_BPP;
        const int N = fp ? N_FP : N_PANO;
        const int* cnt = fp ? g_cnt_fp : g_cnt;
        int* off = fp ? g_off_fp : g_off;
        int* cur = fp ? g_cur_fp : g_cur;
        int seg0 = fp ? SCAN_BPP : 0;
        int segN = fp ? SCAN_BLKS : SCAN_BPP;
        int base = (fp ? blk - SCAN_BPP : blk) * 1024;
        int lane = t & 31, wid = t >> 5;
        int idx = base + t * 4;
        int4 v = make_int4(0, 0, 0, 0);
        if (idx < N) v = *(const int4*)&cnt[idx];
        int s0 = v.x, s1 = v.x + v.y, s2 = s1 + v.z, tot = s2 + v.w;
        int inc = tot;
        #pragma unroll
        for (int o = 1; o < 32; o <<= 1) {
            int n = __shfl_up_sync(0xFFFFFFFFu, inc, o);
            if (lane >= o) inc += n;
        }
        if (lane == 31) woff[wid] = inc;
        __syncthreads();
        if (t == 0) {
            int run = 0;
            #pragma unroll
            for (int j = 0; j < 8; j++) { int x = woff[j]; woff[j] = run; run += x; }
            s_tot = run;
            atomicExch(&g_flagged[blk], run | SCAN_FLAG);
            s_bo = 0;
        }
        __syncthreads();
        if (t < blk - seg0) {
            int j = seg0 + t;
            int w;
            do { w = atomicAdd(&g_flagged[j], 0); } while (!(w & SCAN_FLAG));
            atomicAdd(&s_bo, w & (SCAN_FLAG - 1));
        }
        __syncthreads();
        int bo = s_bo;
        if (t == 0 && blk == segN - 1) off[N] = bo + s_tot;
        int exc = bo + woff[wid] + inc - tot;
        if (idx < N) {
            int4 o = make_int4(exc, exc + s0, exc + s1, exc + s2);
            *(int4*)&off[idx] = o;
            *(int4*)&cur[idx] = o;
        }
    } else if (blk < K2_GEMV2) {
        int gw = ((blk - SCAN_BLKS) * 256 + t) >> 5;
        int lane = t & 31;
        if (gw >= N_PANO) return;
        float4 x = *(const float4*)&X[(size_t)gw * 128 + lane * 4];
        float4 a = *(const float4*)&g_wc[0 + lane * 4];
        float4 b = *(const float4*)&g_wc[128 + lane * 4];
        float sa = x.x * a.x + x.y * a.y + x.z * a.z + x.w * a.w;
        float sb = x.x * b.x + x.y * b.y + x.z * b.z + x.w * b.w;
        #pragma unroll
        for (int o = 16; o; o >>= 1) {
            sa += __shfl_xor_sync(0xFFFFFFFFu, sa, o);
            sb += __shfl_xor_sync(0xFFFFFFFFu, sb, o);
        }
        if (lane == 0) { g_es[gw] = sa; g_ed[gw] = sb; }
    } else {
        int gw = ((blk - K2_GEMV2) * 256 + t) >> 5;
        int lane = t & 31;
        if (gw >= N_FP) return;
        float2 x = *(const float2*)&Xfp[(size_t)gw * 64 + lane * 2];
        float2 a = *(const float2*)&g_wc[640 + lane * 2];
        float s = x.x * a.x + x.y * a.y;
        #pragma unroll
        for (int o = 16; o; o >>= 1) s += __shfl_xor_sync(0xFFFFFFFFu, s, o);
        if (lane == 0) g_edfp[gw] = s;
    }
}

// ---------------- K3: standalone scatter (no smem -> full occupancy) ----------------
__global__ void __launch_bounds__(256) scatter_kernel(
        const int* __restrict__ src_pp, const int* __restrict__ dst_pp,
        const int* __restrict__ src_pf, const int* __restrict__ dst_pf) {
    int i = blockIdx.x * blockDim.x + threadIdx.x;
    if (i < E_PP) {
        int pos = atomicAdd(&g_cur[dst_pp[i]], 1);
        g_srt[pos] = src_pp[i];
    } else if (i < E_PP + E_PF) {
        int j = i - E_PP;
        int pos = atomicAdd(&g_cur_fp[dst_pf[j]], 1);
        g_srt_fp[pos] = src_pf[j];
    }
}

// ---------------- CSR aggregation + finalize + next-stage dots ----------------
__global__ void __launch_bounds__(256) agg_pp_kernel(const float* __restrict__ b,
                                                     const float* __restrict__ Lb,
                                                     const float* __restrict__ es_in,
                                                     const float* __restrict__ ed_in,
                                                     const float* __restrict__ wa,
                                                     const float* __restrict__ wb,
                                                     float* __restrict__ ea,
                                                     float* __restrict__ eb,
                                                     ushort_t* __restrict__ hout) {
    int gw = (blockIdx.x * blockDim.x + threadIdx.x) >> 5;
    int lane = threadIdx.x & 31;
    if (gw >= N_PANO) return;
    int start = g_off[gw];
    int end   = g_off[gw + 1];
    float edd = ed_in[gw];
    float4 acc = make_float4(0.f, 0.f, 0.f, 0.f);
    float exsum = 0.f;
    for (int base = start; base < end; base += 32) {
        int m = end - base; if (m > 32) m = 32;
        int s = 0; float ex = 0.f;
        if (lane < m) {
            s = g_srt[base + lane];
            float ez = es_in[s] + edd;
            float e = ez > 0.f ? ez : 0.2f * ez;
            ex = __expf(e);
        }
        exsum += ex;
        for (int j = 0; j < m; j++) {
            int sj   = __shfl_sync(0xFFFFFFFFu, s, j);
            float xj = __shfl_sync(0xFFFFFFFFu, ex, j);
            uint2 hp = *(const uint2*)&g_hsh[(size_t)sj * 128 + lane * 4];
            float2 f0 = __half22float2(*reinterpret_cast<const __half2*>(&hp.x));
            float2 f1 = __half22float2(*reinterpret_cast<const __half2*>(&hp.y));
            acc.x += f0.x * xj; acc.y += f0.y * xj;
            acc.z += f1.x * xj; acc.w += f1.y * xj;
        }
    }
    #pragma unroll
    for (int o = 16; o; o >>= 1) exsum += __shfl_xor_sync(0xFFFFFFFFu, exsum, o);
    float inv = exsum > 0.f ? 1.f / exsum : 0.f;
    uint2 lp = *(const uint2*)&g_linh[(size_t)gw * 128 + lane * 4];
    float2 l0 = __half22float2(*reinterpret_cast<const __half2*>(&lp.x));
    float2 l1 = __half22float2(*reinterpret_cast<const __half2*>(&lp.y));
    float4 bb = *(const float4*)&b[lane * 4];
    float4 lb = *(const float4*)&Lb[lane * 4];
    float4 r;
    r.x = fmaxf(acc.x * inv + bb.x + l0.x + lb.x, 0.f);
    r.y = fmaxf(acc.y * inv + bb.y + l0.y + lb.y, 0.f);
    r.z = fmaxf(acc.z * inv + bb.z + l1.x + lb.z, 0.f);
    r.w = fmaxf(acc.w * inv + bb.w + l1.y + lb.w, 0.f);
    if (hout) {
        __half2 p0 = __floats2half2_rn(r.x, r.y);
        __half2 p1 = __floats2half2_rn(r.z, r.w);
        uint2 u;
        memcpy(&u.x, &p0, 4); memcpy(&u.y, &p1, 4);
        *(uint2*)&hout[(size_t)gw * 128 + lane * 4] = u;
    } else {
        *(float4*)&g_h[(size_t)gw * 128 + lane * 4] = r;
    }
    float4 a4 = *(const float4*)&wa[lane * 4];
    float sa = r.x * a4.x + r.y * a4.y + r.z * a4.z + r.w * a4.w;
    float sb = 0.f;
    if (eb) {
        float4 b4 = *(const float4*)&wb[lane * 4];
        sb = r.x * b4.x + r.y * b4.y + r.z * b4.z + r.w * b4.w;
    }
    #pragma unroll
    for (int o = 16; o; o >>= 1) {
        sa += __shfl_xor_sync(0xFFFFFFFFu, sa, o);
        sb += __shfl_xor_sync(0xFFFFFFFFu, sb, o);
    }
    if (lane == 0) {
        ea[gw] = sa;
        if (eb) eb[gw] = sb;
    }
}

// ---------------- agg_pf: aggregate h2 (128-wide fp16) -> c[N_FP,128] fp32 ----------------
__global__ void __launch_bounds__(256) agg_pf_kernel() {
    int gw = (blockIdx.x * blockDim.x + threadIdx.x) >> 5;
    int lane = threadIdx.x & 31;
    if (gw >= N_FP) return;
    int start = g_off_fp[gw];
    int end   = g_off_fp[gw + 1];
    float edd = g_edfp[gw];
    float4 acc = make_float4(0.f, 0.f, 0.f, 0.f);
    float exsum = 0.f;
    for (int base = start; base < end; base += 32) {
        int m = end - base; if (m > 32) m = 32;
        int s = 0; float ex = 0.f;
        if (lane < m) {
            s = g_srt_fp[base + lane];
            float ez = g_es3[s] + edd;
            float e = ez > 0.f ? ez : 0.2f * ez;
            ex = __expf(e);
        }
        exsum += ex;
        for (int j = 0; j < m; j++) {
            int sj   = __shfl_sync(0xFFFFFFFFu, s, j);
            float xj = __shfl_sync(0xFFFFFFFFu, ex, j);
            uint2 hp = *(const uint2*)&g_h2h[(size_t)sj * 128 + lane * 4];
            float2 f0 = __half22float2(*reinterpret_cast<const __half2*>(&hp.x));
            float2 f1 = __half22float2(*reinterpret_cast<const __half2*>(&hp.y));
            acc.x += f0.x * xj; acc.y += f0.y * xj;
            acc.z += f1.x * xj; acc.w += f1.y * xj;
        }
    }
    #pragma unroll
    for (int o = 16; o; o >>= 1) exsum += __shfl_xor_sync(0xFFFFFFFFu, exsum, o);
    float inv = exsum > 0.f ? 1.f / exsum : 0.f;
    *(float4*)&g_c[(size_t)gw * 128 + lane * 4] =
        make_float4(acc.x * inv, acc.y * inv, acc.z * inv, acc.w * inv);
}

// ---------------- final: translate GEMM + re-zero counters/flags for next launch ----------------
#define ZERO_BLKS ((N_PANO + N_FP + SCAN_BLKS + 255) / 256)   // 235
__global__ void __launch_bounds__(256) gemmT_zero_kernel(
        const float* __restrict__ A, const ushort_t* __restrict__ B,
        const float* __restrict__ bias, float* __restrict__ out) {
    int blk = blockIdx.x;
    if (blk < FP_MBLKS) {
        gemm_body<64>(blk, 0, A, B, (ushort_t*)0, (ushort_t*)0, bias, out, N_FP);
    } else {
        int i = (blk - FP_MBLKS) * 256 + threadIdx.x;
        if (i < N_PANO) g_cnt[i] = 0;
        else if (i < N_PANO + N_FP) g_cnt_fp[i - N_PANO] = 0;
        else if (i < N_PANO + N_FP + SCAN_BLKS) g_flagged[i - N_PANO - N_FP] = 0;
    }
}

// ---------------- launch ----------------
extern "C" void kernel_launch(void* const* d_in, const int* in_sizes, int n_in,
                              void* d_out, int out_size) {
    const float* x_pano = (const float*)d_in[0];
    const float* x_fp   = (const float*)d_in[1];
    const float* Ws0 = (const float*)d_in[2];
    const float* Wd0 = (const float*)d_in[3];
    const float* as0 = (const float*)d_in[4];
    const float* ad0 = (const float*)d_in[5];
    const float* b0  = (const float*)d_in[6];
    const float* Lw0 = (const float*)d_in[7];
    const float* Lb0 = (const float*)d_in[8];
    const float* Ws1 = (const float*)d_in[9];
    const float* Wd1 = (const float*)d_in[10];
    const float* as1 = (const float*)d_in[11];
    const float* ad1 = (const float*)d_in[12];
    const float* b1  = (const float*)d_in[13];
    const float* Lw1 = (const float*)d_in[14];
    const float* Lb1 = (const float*)d_in[15];
    const float* Wts = (const float*)d_in[16];
    const float* Wtd = (const float*)d_in[17];
    const float* ats = (const float*)d_in[18];
    const float* atd = (const float*)d_in[19];
    const float* bt  = (const float*)d_in[20];
    const int* edge_pp = (const int*)d_in[21];
    const int* pf_src  = (const int*)d_in[22];
    const int* pf_dst  = (const int*)d_in[23];
    const int* pp_src = edge_pp;
    const int* pp_dst = edge_pp + E_PP;

    float *p_h, *p_c, *p_es, *p_ed, *p_es2, *p_ed2, *p_es3, *p_wc;
    cudaGetSymbolAddress((void**)&p_h,    g_h);
    cudaGetSymbolAddress((void**)&p_c,    g_c);
    cudaGetSymbolAddress((void**)&p_es,   g_es);
    cudaGetSymbolAddress((void**)&p_ed,   g_ed);
    cudaGetSymbolAddress((void**)&p_es2,  g_es2);
    cudaGetSymbolAddress((void**)&p_ed2,  g_ed2);
    cudaGetSymbolAddress((void**)&p_es3,  g_es3);
    cudaGetSymbolAddress((void**)&p_wc,   g_wc);
    ushort_t *p_hsh, *p_h2h, *p_linh, *p_wb0, *p_wb1, *p_wbt;
    cudaGetSymbolAddress((void**)&p_hsh,  g_hsh);
    cudaGetSymbolAddress((void**)&p_h2h,  g_h2h);
    cudaGetSymbolAddress((void**)&p_linh, g_linh);
    cudaGetSymbolAddress((void**)&p_wb0,  g_wb0);
    cudaGetSymbolAddress((void**)&p_wb1,  g_wb1);
    cudaGetSymbolAddress((void**)&p_wbt,  g_wbt);

    // K1: weight prep (fp16) + compose + histogram (cnt pre-zeroed invariant)
    prep_hist_kernel<<<K1_TOTAL, 256>>>(Ws0, as0, Wd0, ad0, Lw0,
                                        Ws1, as1, Wd1, ad1, Lw1,
                                        Wts, ats, Wtd, atd,
                                        pp_dst, pf_dst);
    // K2: scan (lookback) + attention dots
    scan_gemv_kernel<<<K2_TOTAL, 256>>>(x_pano, x_fp);
    // K3: scatter (full occupancy, no smem)
    scatter_kernel<<<EALL_BLKS, 256>>>(pp_src, pp_dst, pf_src, pf_dst);
    // K4: layer-0 GEMM
    mmagemm_kernel<128><<<dim3(GEMM_MBLKS, 2), 256>>>(x_pano, p_wb0, p_hsh, p_linh, N_PANO);
    // layer 0 aggregation -> h1 fp32 + layer-1 attention dots
    agg_pp_kernel<<<6250, 256>>>(b0, Lb0, p_es, p_ed, p_wc + 256, p_wc + 384,
                                 p_es2, p_ed2, (ushort_t*)0);
    // layer 1 GEMM
    mmagemm_kernel<128><<<dim3(GEMM_MBLKS, 2), 256>>>(p_h, p_wb1, p_hsh, p_linh, N_PANO);
    // layer 1 aggregation -> h2 fp16 + translate attention dots
    agg_pp_kernel<<<6250, 256>>>(b1, Lb1, p_es2, p_ed2, p_wc + 512, (const float*)0,
                                 p_es3, (float*)0, p_h2h);
    // translate: aggregate-then-project
    agg_pf_kernel<<<1250, 256>>>();
    gemmT_zero_kernel<<<FP_MBLKS + ZERO_BLKS, 256>>>(p_c, p_wbt, bt, (float*)d_out);
}

// round 15
// speedup vs baseline: 1.1948x; 1.0330x over previous
#include <cuda_runtime.h>
#include <cuda_bf16.h>
#include <cuda_fp16.h>
#include <math.h>
#include <stdint.h>
#include <string.h>

#define N_PANO 50000
#define N_FP   10000
#define HID    128
#define E_PP   800000
#define E_PF   50000

#define SCAN_BPP 49
#define SCAN_BFP 10
#define SCAN_BLKS (SCAN_BPP + SCAN_BFP)
#define SCAN_FLAG (1 << 30)

#define GEMM_MBLKS 391        // ceil(50000/128)
#define FP_MBLKS   79         // ceil(10000/128)
#define EALL_BLKS  3321       // ceil(850000/256)

typedef unsigned short ushort_t;

// ---------------- device scratch (static, no allocation; zero-init guaranteed) ----------------
// A images padded by 128 rows (GEMM loads full 128-row tiles unconditionally)
__device__ ushort_t g_ahi[(N_PANO + 128) * 128];
__device__ ushort_t g_alo[(N_PANO + 128) * 128];
__device__ ushort_t g_hsh[N_PANO * HID];    // hs fp16 (gather payload)
__device__ ushort_t g_h2h[N_PANO * HID];    // h2 fp16 (translate gather payload)
__device__ ushort_t g_linh[N_PANO * HID];   // lin fp16
__device__ float    g_c[N_FP * 128];        // aggregated h2 per fp node (fp32)
__device__ float g_es[N_PANO];
__device__ float g_ed[N_PANO];
__device__ float g_es2[N_PANO];
__device__ float g_ed2[N_PANO];
__device__ float g_es3[N_PANO];
__device__ float g_edfp[N_FP];
__device__ float g_wc[704];
// fp16 weight images, [N][K] row-major
__device__ ushort_t g_wb0[256 * 128];
__device__ ushort_t g_wb1[256 * 128];
__device__ ushort_t g_wbt[64 * 128];
// CSR build (zero-init at load; re-zeroed by final kernel each launch)
__device__ int g_cnt[N_PANO];
__device__ int g_off[N_PANO + 1];
__device__ int g_cur[N_PANO];
__device__ int g_srt[E_PP];
__device__ int g_cnt_fp[N_FP];
__device__ int g_off_fp[N_FP + 1];
__device__ int g_cur_fp[N_FP];
__device__ int g_srt_fp[E_PF];
__device__ int g_flagged[SCAN_BLKS];

// ---------------- helpers ----------------
__device__ __forceinline__ uint32_t smem_u32(const void* p) {
    uint32_t a;
    asm("{ .reg .u64 t; cvta.to.shared.u64 t, %1; cvt.u32.u64 %0, t; }" : "=r"(a) : "l"(p));
    return a;
}
__device__ __forceinline__ void ldsm_x4(uint32_t* r, uint32_t addr) {
    asm volatile("ldmatrix.sync.aligned.m8n8.x4.shared.b16 {%0,%1,%2,%3}, [%4];"
                 : "=r"(r[0]), "=r"(r[1]), "=r"(r[2]), "=r"(r[3]) : "r"(addr));
}
__device__ __forceinline__ void ldsm_x2(uint32_t* r, uint32_t addr) {
    asm volatile("ldmatrix.sync.aligned.m8n8.x2.shared.b16 {%0,%1}, [%2];"
                 : "=r"(r[0]), "=r"(r[1]) : "r"(addr));
}
__device__ __forceinline__ void mma16816f(float* d, const uint32_t* a, const uint32_t* b) {
    asm volatile("mma.sync.aligned.m16n8k16.row.col.f32.f16.f16.f32 "
                 "{%0,%1,%2,%3}, {%4,%5,%6,%7}, {%8,%9}, {%0,%1,%2,%3};"
                 : "+f"(d[0]), "+f"(d[1]), "+f"(d[2]), "+f"(d[3])
                 : "r"(a[0]), "r"(a[1]), "r"(a[2]), "r"(a[3]), "r"(b[0]), "r"(b[1]));
}
__device__ __forceinline__ void split_f16(float v, ushort_t& h, ushort_t& l) {
    __half hb = __float2half_rn(v);
    float r = v - __half2float(hb);
    __half lb = __float2half_rn(r);
    memcpy(&h, &hb, 2); memcpy(&l, &lb, 2);
}

// ---------------- pipelined GEMM: pre-split fp16 A images, single fp16 B, 2 terms ----------------
// C[M,256] over grid.y in {0,1}; fp16 outputs C1h/C2h, stride 128.
__global__ void __launch_bounds__(256, 2) gemmP_kernel(
        const ushort_t* __restrict__ Ahi, const ushort_t* __restrict__ Alo,
        const ushort_t* __restrict__ B,
        ushort_t* __restrict__ C1h, ushort_t* __restrict__ C2h, int M) {
    __shared__ ushort_t As[2][128][40];
    __shared__ ushort_t Bs[128][40];
    const int tid = threadIdx.x;
    const int wid = tid >> 5, lane = tid & 31;
    const int wm = wid >> 2, wn = wid & 3;
    const int m0 = blockIdx.x * 128;
    const int nb = blockIdx.y * 128;
    const int rr = tid >> 2, qq = (tid & 3) * 8;   // chunk row / half-offset

    const ushort_t* gAh0 = Ahi + (size_t)(m0 + rr) * 128 + qq;
    const ushort_t* gAh1 = gAh0 + 64 * 128;
    const ushort_t* gAl0 = Alo + (size_t)(m0 + rr) * 128 + qq;
    const ushort_t* gAl1 = gAl0 + 64 * 128;
    const ushort_t* gB0  = B + (size_t)(nb + rr) * 128 + qq;
    const ushort_t* gB1  = gB0 + 64 * 128;

    float d[4][4][4];
    #pragma unroll
    for (int mt = 0; mt < 4; mt++)
        #pragma unroll
        for (int nt = 0; nt < 4; nt++)
            #pragma unroll
            for (int j = 0; j < 4; j++) d[mt][nt][j] = 0.f;

    uint4 va0, va1, vl0, vl1, vb0, vb1;
    // prologue: stage 0
    va0 = *(const uint4*)(gAh0); va1 = *(const uint4*)(gAh1);
    vl0 = *(const uint4*)(gAl0); vl1 = *(const uint4*)(gAl1);
    vb0 = *(const uint4*)(gB0);  vb1 = *(const uint4*)(gB1);
    *(uint4*)&As[0][rr][qq] = va0; *(uint4*)&As[0][rr + 64][qq] = va1;
    *(uint4*)&As[1][rr][qq] = vl0; *(uint4*)&As[1][rr + 64][qq] = vl1;
    *(uint4*)&Bs[rr][qq] = vb0;    *(uint4*)&Bs[rr + 64][qq] = vb1;
    __syncthreads();

    #pragma unroll
    for (int i = 0; i < 4; i++) {
        if (i < 3) {
            int k0 = (i + 1) * 32;
            va0 = *(const uint4*)(gAh0 + k0); va1 = *(const uint4*)(gAh1 + k0);
            vl0 = *(const uint4*)(gAl0 + k0); vl1 = *(const uint4*)(gAl1 + k0);
            vb0 = *(const uint4*)(gB0 + k0);  vb1 = *(const uint4*)(gB1 + k0);
        }
        #pragma unroll
        for (int kk = 0; kk < 32; kk += 16) {
            uint32_t ah[4][4], al[4][4], bh[4][2];
            #pragma unroll
            for (int mt = 0; mt < 4; mt++) {
                int ar = wm * 64 + mt * 16 + (lane & 15);
                int ac = kk + (lane >> 4) * 8;
                ldsm_x4(ah[mt], smem_u32(&As[0][ar][ac]));
                ldsm_x4(al[mt], smem_u32(&As[1][ar][ac]));
            }
            #pragma unroll
            for (int nt = 0; nt < 4; nt++) {
                int l16 = lane & 15;
                int br = wn * 32 + nt * 8 + (l16 & 7);
                int bc = kk + (l16 >> 3) * 8;
                ldsm_x2(bh[nt], smem_u32(&Bs[br][bc]));
            }
            #pragma unroll
            for (int mt = 0; mt < 4; mt++)
                #pragma unroll
                for (int nt = 0; nt < 4; nt++) {
                    mma16816f(d[mt][nt], ah[mt], bh[nt]);
                    mma16816f(d[mt][nt], al[mt], bh[nt]);
                }
        }
        if (i < 3) {
            __syncthreads();
            *(uint4*)&As[0][rr][qq] = va0; *(uint4*)&As[0][rr + 64][qq] = va1;
            *(uint4*)&As[1][rr][qq] = vl0; *(uint4*)&As[1][rr + 64][qq] = vl1;
            *(uint4*)&Bs[rr][qq] = vb0;    *(uint4*)&Bs[rr + 64][qq] = vb1;
            __syncthreads();
        }
    }

    ushort_t* C = (blockIdx.y == 0) ? C1h : C2h;
    #pragma unroll
    for (int mt = 0; mt < 4; mt++) {
        int r0 = m0 + wm * 64 + mt * 16 + (lane >> 2);
        #pragma unroll
        for (int nt = 0; nt < 4; nt++) {
            int c = wn * 32 + nt * 8 + (lane & 3) * 2;
            if (r0 < M)
                *reinterpret_cast<__half2*>(&C[(size_t)r0 * 128 + c]) =
                    __floats2half2_rn(d[mt][nt][0], d[mt][nt][1]);
            if (r0 + 8 < M)
                *reinterpret_cast<__half2*>(&C[(size_t)(r0 + 8) * 128 + c]) =
                    __floats2half2_rn(d[mt][nt][2], d[mt][nt][3]);
        }
    }
}

// ---------------- translate GEMM body (fp32 A, in-kernel split, NT=64, fp32 out+bias) ----------------
__device__ __forceinline__ void gemmT_body(
        int bx, const float* __restrict__ A, const ushort_t* __restrict__ B,
        const float* __restrict__ bias, float* __restrict__ Cf, int M) {
    __shared__ ushort_t As[2][128][40];
    __shared__ ushort_t Bs[64][40];
    const int tid = threadIdx.x;
    const int wid = tid >> 5, lane = tid & 31;
    const int wm = wid >> 2, wn = wid & 3;
    const int m0 = bx * 128;

    float d[4][2][4];
    #pragma unroll
    for (int mt = 0; mt < 4; mt++)
        #pragma unroll
        for (int nt = 0; nt < 2; nt++)
            #pragma unroll
            for (int j = 0; j < 4; j++) d[mt][nt][j] = 0.f;

    #pragma unroll 1
    for (int k0 = 0; k0 < 128; k0 += 32) {
        #pragma unroll
        for (int l = 0; l < 4; l++) {
            int i = tid + l * 256;
            int r = i >> 3, cq = (i & 7) * 4;
            float4 v = make_float4(0.f, 0.f, 0.f, 0.f);
            if (m0 + r < M) v = *(const float4*)&A[(size_t)(m0 + r) * 128 + k0 + cq];
            ushort4 h4, l4;
            split_f16(v.x, h4.x, l4.x); split_f16(v.y, h4.y, l4.y);
            split_f16(v.z, h4.z, l4.z); split_f16(v.w, h4.w, l4.w);
            *(ushort4*)&As[0][r][cq] = h4;
            *(ushort4*)&As[1][r][cq] = l4;
        }
        if (tid < 256) {
            int c = tid;                       // 64*4 = 256 chunks
            int r = c >> 2, q = (c & 3) * 8;
            *(uint4*)&Bs[r][q] = *(const uint4*)&B[(size_t)r * 128 + k0 + q];
        }
        __syncthreads();
        #pragma unroll
        for (int kk = 0; kk < 32; kk += 16) {
            uint32_t ah[4][4], al[4][4], bh[2][2];
            #pragma unroll
            for (int mt = 0; mt < 4; mt++) {
                int ar = wm * 64 + mt * 16 + (lane & 15);
                int ac = kk + (lane >> 4) * 8;
                ldsm_x4(ah[mt], smem_u32(&As[0][ar][ac]));
                ldsm_x4(al[mt], smem_u32(&As[1][ar][ac]));
            }
            #pragma unroll
            for (int nt = 0; nt < 2; nt++) {
                int l16 = lane & 15;
                int br = wn * 16 + nt * 8 + (l16 & 7);
                int bc = kk + (l16 >> 3) * 8;
                ldsm_x2(bh[nt], smem_u32(&Bs[br][bc]));
            }
            #pragma unroll
            for (int mt = 0; mt < 4; mt++)
                #pragma unroll
                for (int nt = 0; nt < 2; nt++) {
                    mma16816f(d[mt][nt], ah[mt], bh[nt]);
                    mma16816f(d[mt][nt], al[mt], bh[nt]);
                }
        }
        __syncthreads();
    }
    #pragma unroll
    for (int mt = 0; mt < 4; mt++) {
        int r0 = m0 + wm * 64 + mt * 16 + (lane >> 2);
        #pragma unroll
        for (int nt = 0; nt < 2; nt++) {
            int c = wn * 16 + nt * 8 + (lane & 3) * 2;
            float b0 = __ldg(&bias[c]), b1 = __ldg(&bias[c + 1]);
            if (r0 < M)
                *(float2*)&Cf[(size_t)r0 * 64 + c] = make_float2(d[mt][nt][0] + b0,
                                                                 d[mt][nt][1] + b1);
            if (r0 + 8 < M)
                *(float2*)&Cf[(size_t)(r0 + 8) * 64 + c] = make_float2(d[mt][nt][2] + b0,
                                                                       d[mt][nt][3] + b1);
        }
    }
}

// ---------------- K1: weight prep (fp16) + compose + histogram ----------------
#define K1_W     288
#define K1_COMP  (K1_W + 3)
#define K1_HPP   (K1_COMP + 782)
#define K1_TOTAL (K1_HPP + 49)
__global__ void __launch_bounds__(256) prep_hist_kernel(
        const float* __restrict__ Ws0, const float* __restrict__ as0,
        const float* __restrict__ Wd0, const float* __restrict__ ad0,
        const float* __restrict__ Lw0,
        const float* __restrict__ Ws1, const float* __restrict__ as1,
        const float* __restrict__ Wd1, const float* __restrict__ ad1,
        const float* __restrict__ Lw1,
        const float* __restrict__ Wts, const float* __restrict__ ats,
        const float* __restrict__ Wtd, const float* __restrict__ atd,
        const int* __restrict__ dst_pp, const int* __restrict__ dst_pf) {
    int blk = blockIdx.x;
    int t = threadIdx.x;
    if (blk < K1_W) {
        int idx = blk * 256 + t;
        ushort_t* img;
        int n, k;
        float v;
        if (idx < 32768) {
            n = idx >> 7; k = idx & 127;
            v = (n < 128) ? Ws0[k * 128 + n] : Lw0[k * 128 + (n - 128)];
            img = g_wb0;
        } else if (idx < 65536) {
            int e = idx - 32768;
            n = e >> 7; k = e & 127;
            v = (n < 128) ? Ws1[k * 128 + n] : Lw1[k * 128 + (n - 128)];
            img = g_wb1;
        } else {
            int e = idx - 65536;
            n = e >> 7; k = e & 127;
            v = Wts[k * 64 + n];
            img = g_wbt;
        }
        __half hv = __float2half_rn(v);
        ushort_t u; memcpy(&u, &hv, 2);
        img[n * 128 + k] = u;
    } else if (blk < K1_COMP) {
        int b = blk - K1_W;
        if (b == 0) {
            if (t < 128) {
                float s = 0.f;
                for (int n = 0; n < 128; n++) s += Ws0[t * 128 + n] * as0[n];
                g_wc[t] = s;
            } else {
                int i = t - 128; float s = 0.f;
                for (int n = 0; n < 128; n++) s += Wd0[i * 128 + n] * ad0[n];
                g_wc[128 + i] = s;
            }
        } else if (b == 1) {
            if (t < 128) {
                float s = 0.f;
                for (int n = 0; n < 128; n++) s += Ws1[t * 128 + n] * as1[n];
                g_wc[256 + t] = s;
            } else {
                int i = t - 128; float s = 0.f;
                for (int n = 0; n < 128; n++) s += Wd1[i * 128 + n] * ad1[n];
                g_wc[384 + i] = s;
            }
        } else {
            if (t < 128) {
                float s = 0.f;
                for (int n = 0; n < 64; n++) s += Wts[t * 64 + n] * ats[n];
                g_wc[512 + t] = s;
            } else if (t < 192) {
                int i = t - 128; float s = 0.f;
                for (int n = 0; n < 64; n++) s += Wtd[i * 64 + n] * atd[n];
                g_wc[640 + i] = s;
            }
        }
    } else if (blk < K1_HPP) {
        int g = (blk - K1_COMP) * 256 + t;
        if (g * 4 < E_PP) {
            int4 d = *(const int4*)&dst_pp[g * 4];
            atomicAdd(&g_cnt[d.x], 1);
            atomicAdd(&g_cnt[d.y], 1);
            atomicAdd(&g_cnt[d.z], 1);
            atomicAdd(&g_cnt[d.w], 1);
        }
    } else {
        int g = (blk - K1_HPP) * 256 + t;
        if (g * 4 < E_PF) {
            int4 d = *(const int4*)&dst_pf[g * 4];
            atomicAdd(&g_cnt_fp[d.x], 1);
            atomicAdd(&g_cnt_fp[d.y], 1);
            atomicAdd(&g_cnt_fp[d.z], 1);
            atomicAdd(&g_cnt_fp[d.w], 1);
        }
    }
}

// ---------------- K2: fused scan + attention GEMVs + x_pano fp16 split ----------------
#define K2_GEMV2 (SCAN_BLKS + 6250)
#define K2_TOTAL (K2_GEMV2 + 1250)
__global__ void __launch_bounds__(256) scan_gemv_kernel(
        const float* __restrict__ X, const float* __restrict__ Xfp) {
    int blk = blockIdx.x;
    int t = threadIdx.x;
    if (blk < SCAN_BLKS) {
        __shared__ int woff[9];
        __shared__ int s_bo;
        __shared__ int s_tot;
        bool fp = blk >= SCAN_BPP;
        const int N = fp ? N_FP : N_PANO;
        const int* cnt = fp ? g_cnt_fp : g_cnt;
        int* off = fp ? g_off_fp : g_off;
        int* cur = fp ? g_cur_fp : g_cur;
        int seg0 = fp ? SCAN_BPP : 0;
        int segN = fp ? SCAN_BLKS : SCAN_BPP;
        int base = (fp ? blk - SCAN_BPP : blk) * 1024;
        int lane = t & 31, wid = t >> 5;
        int idx = base + t * 4;
        int4 v = make_int4(0, 0, 0, 0);
        if (idx < N) v = *(const int4*)&cnt[idx];
        int s0 = v.x, s1 = v.x + v.y, s2 = s1 + v.z, tot = s2 + v.w;
        int inc = tot;
        #pragma unroll
        for (int o = 1; o < 32; o <<= 1) {
            int n = __shfl_up_sync(0xFFFFFFFFu, inc, o);
            if (lane >= o) inc += n;
        }
        if (lane == 31) woff[wid] = inc;
        __syncthreads();
        if (t == 0) {
            int run = 0;
            #pragma unroll
            for (int j = 0; j < 8; j++) { int x = woff[j]; woff[j] = run; run += x; }
            s_tot = run;
            atomicExch(&g_flagged[blk], run | SCAN_FLAG);
            s_bo = 0;
        }
        __syncthreads();
        if (t < blk - seg0) {
            int j = seg0 + t;
            int w;
            do { w = atomicAdd(&g_flagged[j], 0); } while (!(w & SCAN_FLAG));
            atomicAdd(&s_bo, w & (SCAN_FLAG - 1));
        }
        __syncthreads();
        int bo = s_bo;
        if (t == 0 && blk == segN - 1) off[N] = bo + s_tot;
        int exc = bo + woff[wid] + inc - tot;
        if (idx < N) {
            int4 o = make_int4(exc, exc + s0, exc + s1, exc + s2);
            *(int4*)&off[idx] = o;
            *(int4*)&cur[idx] = o;
        }
    } else if (blk < K2_GEMV2) {
        int gw = ((blk - SCAN_BLKS) * 256 + t) >> 5;
        int lane = t & 31;
        if (gw >= N_PANO) return;
        float4 x = *(const float4*)&X[(size_t)gw * 128 + lane * 4];
        // split x_pano into fp16 hi/lo A images for the layer-0 GEMM
        ushort4 h4, l4;
        split_f16(x.x, h4.x, l4.x); split_f16(x.y, h4.y, l4.y);
        split_f16(x.z, h4.z, l4.z); split_f16(x.w, h4.w, l4.w);
        *(ushort4*)&g_ahi[(size_t)gw * 128 + lane * 4] = h4;
        *(ushort4*)&g_alo[(size_t)gw * 128 + lane * 4] = l4;
        float4 a = *(const float4*)&g_wc[0 + lane * 4];
        float4 b = *(const float4*)&g_wc[128 + lane * 4];
        float sa = x.x * a.x + x.y * a.y + x.z * a.z + x.w * a.w;
        float sb = x.x * b.x + x.y * b.y + x.z * b.z + x.w * b.w;
        #pragma unroll
        for (int o = 16; o; o >>= 1) {
            sa += __shfl_xor_sync(0xFFFFFFFFu, sa, o);
            sb += __shfl_xor_sync(0xFFFFFFFFu, sb, o);
        }
        if (lane == 0) { g_es[gw] = sa; g_ed[gw] = sb; }
    } else {
        int gw = ((blk - K2_GEMV2) * 256 + t) >> 5;
        int lane = t & 31;
        if (gw >= N_FP) return;
        float2 x = *(const float2*)&Xfp[(size_t)gw * 64 + lane * 2];
        float2 a = *(const float2*)&g_wc[640 + lane * 2];
        float s = x.x * a.x + x.y * a.y;
        #pragma unroll
        for (int o = 16; o; o >>= 1) s += __shfl_xor_sync(0xFFFFFFFFu, s, o);
        if (lane == 0) g_edfp[gw] = s;
    }
}

// ---------------- K3: standalone scatter ----------------
__global__ void __launch_bounds__(256) scatter_kernel(
        const int* __restrict__ src_pp, const int* __restrict__ dst_pp,
        const int* __restrict__ src_pf, const int* __restrict__ dst_pf) {
    int i = blockIdx.x * blockDim.x + threadIdx.x;
    if (i < E_PP) {
        int pos = atomicAdd(&g_cur[dst_pp[i]], 1);
        g_srt[pos] = src_pp[i];
    } else if (i < E_PP + E_PF) {
        int j = i - E_PP;
        int pos = atomicAdd(&g_cur_fp[dst_pf[j]], 1);
        g_srt_fp[pos] = src_pf[j];
    }
}

// ---------------- CSR aggregation + finalize + next-stage dots ----------------
// img_hi != 0: write h as split fp16 hi/lo images (feeds next GEMM).
// else: write h fp16 to hout (gather payload for translate).
__global__ void __launch_bounds__(256) agg_pp_kernel(const float* __restrict__ b,
                                                     const float* __restrict__ Lb,
                                                     const float* __restrict__ es_in,
                                                     const float* __restrict__ ed_in,
                                                     const float* __restrict__ wa,
                                                     const float* __restrict__ wb,
                                                     float* __restrict__ ea,
                                                     float* __restrict__ eb,
                                                     ushort_t* __restrict__ img_hi,
                                                     ushort_t* __restrict__ img_lo,
                                                     ushort_t* __restrict__ hout) {
    int gw = (blockIdx.x * blockDim.x + threadIdx.x) >> 5;
    int lane = threadIdx.x & 31;
    if (gw >= N_PANO) return;
    int start = g_off[gw];
    int end   = g_off[gw + 1];
    float edd = ed_in[gw];
    float4 acc = make_float4(0.f, 0.f, 0.f, 0.f);
    float exsum = 0.f;
    for (int base = start; base < end; base += 32) {
        int m = end - base; if (m > 32) m = 32;
        int s = 0; float ex = 0.f;
        if (lane < m) {
            s = g_srt[base + lane];
            float ez = es_in[s] + edd;
            float e = ez > 0.f ? ez : 0.2f * ez;
            ex = __expf(e);
        }
        exsum += ex;
        for (int j = 0; j < m; j++) {
            int sj   = __shfl_sync(0xFFFFFFFFu, s, j);
            float xj = __shfl_sync(0xFFFFFFFFu, ex, j);
            uint2 hp = *(const uint2*)&g_hsh[(size_t)sj * 128 + lane * 4];
            float2 f0 = __half22float2(*reinterpret_cast<const __half2*>(&hp.x));
            float2 f1 = __half22float2(*reinterpret_cast<const __half2*>(&hp.y));
            acc.x += f0.x * xj; acc.y += f0.y * xj;
            acc.z += f1.x * xj; acc.w += f1.y * xj;
        }
    }
    #pragma unroll
    for (int o = 16; o; o >>= 1) exsum += __shfl_xor_sync(0xFFFFFFFFu, exsum, o);
    float inv = exsum > 0.f ? 1.f / exsum : 0.f;
    uint2 lp = *(const uint2*)&g_linh[(size_t)gw * 128 + lane * 4];
    float2 l0 = __half22float2(*reinterpret_cast<const __half2*>(&lp.x));
    float2 l1 = __half22float2(*reinterpret_cast<const __half2*>(&lp.y));
    float4 bb = *(const float4*)&b[lane * 4];
    float4 lb = *(const float4*)&Lb[lane * 4];
    float4 r;
    r.x = fmaxf(acc.x * inv + bb.x + l0.x + lb.x, 0.f);
    r.y = fmaxf(acc.y * inv + bb.y + l0.y + lb.y, 0.f);
    r.z = fmaxf(acc.z * inv + bb.z + l1.x + lb.z, 0.f);
    r.w = fmaxf(acc.w * inv + bb.w + l1.y + lb.w, 0.f);
    if (img_hi) {
        ushort4 h4, l4;
        split_f16(r.x, h4.x, l4.x); split_f16(r.y, h4.y, l4.y);
        split_f16(r.z, h4.z, l4.z); split_f16(r.w, h4.w, l4.w);
        *(ushort4*)&img_hi[(size_t)gw * 128 + lane * 4] = h4;
        *(ushort4*)&img_lo[(size_t)gw * 128 + lane * 4] = l4;
    } else {
        __half2 p0 = __floats2half2_rn(r.x, r.y);
        __half2 p1 = __floats2half2_rn(r.z, r.w);
        uint2 u;
        memcpy(&u.x, &p0, 4); memcpy(&u.y, &p1, 4);
        *(uint2*)&hout[(size_t)gw * 128 + lane * 4] = u;
    }
    float4 a4 = *(const float4*)&wa[lane * 4];
    float sa = r.x * a4.x + r.y * a4.y + r.z * a4.z + r.w * a4.w;
    float sb = 0.f;
    if (eb) {
        float4 b4 = *(const float4*)&wb[lane * 4];
        sb = r.x * b4.x + r.y * b4.y + r.z * b4.z + r.w * b4.w;
    }
    #pragma unroll
    for (int o = 16; o; o >>= 1) {
        sa += __shfl_xor_sync(0xFFFFFFFFu, sa, o);
        sb += __shfl_xor_sync(0xFFFFFFFFu, sb, o);
    }
    if (lane == 0) {
        ea[gw] = sa;
        if (eb) eb[gw] = sb;
    }
}

// ---------------- agg_pf: aggregate h2 -> c[N_FP,128] fp32 ----------------
__global__ void __launch_bounds__(256) agg_pf_kernel() {
    int gw = (blockIdx.x * blockDim.x + threadIdx.x) >> 5;
    int lane = threadIdx.x & 31;
    if (gw >= N_FP) return;
    int start = g_off_fp[gw];
    int end   = g_off_fp[gw + 1];
    float edd = g_edfp[gw];
    float4 acc = make_float4(0.f, 0.f, 0.f, 0.f);
    float exsum = 0.f;
    for (int base = start; base < end; base += 32) {
        int m = end - base; if (m > 32) m = 32;
        int s = 0; float ex = 0.f;
        if (lane < m) {
            s = g_srt_fp[base + lane];
            float ez = g_es3[s] + edd;
            float e = ez > 0.f ? ez : 0.2f * ez;
            ex = __expf(e);
        }
        exsum += ex;
        for (int j = 0; j < m; j++) {
            int sj   = __shfl_sync(0xFFFFFFFFu, s, j);
            float xj = __shfl_sync(0xFFFFFFFFu, ex, j);
            uint2 hp = *(const uint2*)&g_h2h[(size_t)sj * 128 + lane * 4];
            float2 f0 = __half22float2(*reinterpret_cast<const __half2*>(&hp.x));
            float2 f1 = __half22float2(*reinterpret_cast<const __half2*>(&hp.y));
            acc.x += f0.x * xj; acc.y += f0.y * xj;
            acc.z += f1.x * xj; acc.w += f1.y * xj;
        }
    }
    #pragma unroll
    for (int o = 16; o; o >>= 1) exsum += __shfl_xor_sync(0xFFFFFFFFu, exsum, o);
    float inv = exsum > 0.f ? 1.f / exsum : 0.f;
    *(float4*)&g_c[(size_t)gw * 128 + lane * 4] =
        make_float4(acc.x * inv, acc.y * inv, acc.z * inv, acc.w * inv);
}

// ---------------- final: translate GEMM + re-zero counters/flags for next launch ----------------
#define ZERO_BLKS ((N_PANO + N_FP + SCAN_BLKS + 255) / 256)
__global__ void __launch_bounds__(256) gemmT_zero_kernel(
        const float* __restrict__ A, const ushort_t* __restrict__ B,
        const float* __restrict__ bias, float* __restrict__ out) {
    int blk = blockIdx.x;
    if (blk < FP_MBLKS) {
        gemmT_body(blk, A, B, bias, out, N_FP);
    } else {
        int i = (blk - FP_MBLKS) * 256 + threadIdx.x;
        if (i < N_PANO) g_cnt[i] = 0;
        else if (i < N_PANO + N_FP) g_cnt_fp[i - N_PANO] = 0;
        else if (i < N_PANO + N_FP + SCAN_BLKS) g_flagged[i - N_PANO - N_FP] = 0;
    }
}

// ---------------- launch ----------------
extern "C" void kernel_launch(void* const* d_in, const int* in_sizes, int n_in,
                              void* d_out, int out_size) {
    const float* x_pano = (const float*)d_in[0];
    const float* x_fp   = (const float*)d_in[1];
    const float* Ws0 = (const float*)d_in[2];
    const float* Wd0 = (const float*)d_in[3];
    const float* as0 = (const float*)d_in[4];
    const float* ad0 = (const float*)d_in[5];
    const float* b0  = (const float*)d_in[6];
    const float* Lw0 = (const float*)d_in[7];
    const float* Lb0 = (const float*)d_in[8];
    const float* Ws1 = (const float*)d_in[9];
    const float* Wd1 = (const float*)d_in[10];
    const float* as1 = (const float*)d_in[11];
    const float* ad1 = (const float*)d_in[12];
    const float* b1  = (const float*)d_in[13];
    const float* Lw1 = (const float*)d_in[14];
    const float* Lb1 = (const float*)d_in[15];
    const float* Wts = (const float*)d_in[16];
    const float* Wtd = (const float*)d_in[17];
    const float* ats = (const float*)d_in[18];
    const float* atd = (const float*)d_in[19];
    const float* bt  = (const float*)d_in[20];
    const int* edge_pp = (const int*)d_in[21];
    const int* pf_src  = (const int*)d_in[22];
    const int* pf_dst  = (const int*)d_in[23];
    const int* pp_src = edge_pp;
    const int* pp_dst = edge_pp + E_PP;

    float *p_c, *p_es, *p_ed, *p_es2, *p_ed2, *p_es3, *p_wc;
    cudaGetSymbolAddress((void**)&p_c,    g_c);
    cudaGetSymbolAddress((void**)&p_es,   g_es);
    cudaGetSymbolAddress((void**)&p_ed,   g_ed);
    cudaGetSymbolAddress((void**)&p_es2,  g_es2);
    cudaGetSymbolAddress((void**)&p_ed2,  g_ed2);
    cudaGetSymbolAddress((void**)&p_es3,  g_es3);
    cudaGetSymbolAddress((void**)&p_wc,   g_wc);
    ushort_t *p_ahi, *p_alo, *p_hsh, *p_h2h, *p_linh, *p_wb0, *p_wb1, *p_wbt;
    cudaGetSymbolAddress((void**)&p_ahi,  g_ahi);
    cudaGetSymbolAddress((void**)&p_alo,  g_alo);
    cudaGetSymbolAddress((void**)&p_hsh,  g_hsh);
    cudaGetSymbolAddress((void**)&p_h2h,  g_h2h);
    cudaGetSymbolAddress((void**)&p_linh, g_linh);
    cudaGetSymbolAddress((void**)&p_wb0,  g_wb0);
    cudaGetSymbolAddress((void**)&p_wb1,  g_wb1);
    cudaGetSymbolAddress((void**)&p_wbt,  g_wbt);

    // K1: weight prep (fp16) + compose + histogram
    prep_hist_kernel<<<K1_TOTAL, 256>>>(Ws0, as0, Wd0, ad0, Lw0,
                                        Ws1, as1, Wd1, ad1, Lw1,
                                        Wts, ats, Wtd, atd,
                                        pp_dst, pf_dst);
    // K2: scan + attention dots + x_pano split
    scan_gemv_kernel<<<K2_TOTAL, 256>>>(x_pano, x_fp);
    // K3: scatter
    scatter_kernel<<<EALL_BLKS, 256>>>(pp_src, pp_dst, pf_src, pf_dst);
    // K4: layer-0 GEMM (register-prefetch pipelined)
    gemmP_kernel<<<dim3(GEMM_MBLKS, 2), 256>>>(p_ahi, p_alo, p_wb0, p_hsh, p_linh, N_PANO);
    // layer 0 aggregation -> split A images + layer-1 attention dots
    agg_pp_kernel<<<6250, 256>>>(b0, Lb0, p_es, p_ed, p_wc + 256, p_wc + 384,
                                 p_es2, p_ed2, p_ahi, p_alo, (ushort_t*)0);
    // layer 1 GEMM
    gemmP_kernel<<<dim3(GEMM_MBLKS, 2), 256>>>(p_ahi, p_alo, p_wb1, p_hsh, p_linh, N_PANO);
    // layer 1 aggregation -> h2 fp16 + translate attention dots
    agg_pp_kernel<<<6250, 256>>>(b1, Lb1, p_es2, p_ed2, p_wc + 512, (const float*)0,
                                 p_es3, (float*)0, (ushort_t*)0, (ushort_t*)0, p_h2h);
    // translate: aggregate-then-project
    agg_pf_kernel<<<1250, 256>>>();
    gemmT_zero_kernel<<<FP_MBLKS + ZERO_BLKS, 256>>>(p_c, p_wbt, bt, (float*)d_out);
}